// round 1
// baseline (speedup 1.0000x reference)
#include <cuda_runtime.h>
#include <cstdint>

#define BB 8
#define NQ 1024
#define NKV 1024
#define DIM 1024
#define NH 16
#define HD 64
#define M_TOT (BB*NQ)   // 8192
#define QTILE 32
#define KTILE 64
#define SPAD 1025       // padded score row stride (floats)

// Scratch (allocation-free rule: __device__ globals)
__device__ float g_Q [M_TOT*DIM];
__device__ float g_K [M_TOT*DIM];
__device__ float g_V [M_TOT*DIM];
__device__ float g_AO[M_TOT*DIM];

// ---------------------------------------------------------------------------
// Zero a float buffer
// ---------------------------------------------------------------------------
__global__ void zero_kernel(float* __restrict__ p, int n) {
    int i = blockIdx.x * blockDim.x + threadIdx.x;
    int stride = gridDim.x * blockDim.x;
    for (; i < n; i += stride) p[i] = 0.0f;
}

// ---------------------------------------------------------------------------
// GEMM: Y[M,N] = X[M,K] @ W[N,K]^T + bias[N]
// 64x64 block tile, KT=16 staging, 4x4 per-thread micro-tile, 256 threads.
// ---------------------------------------------------------------------------
#define GKT 16
__global__ void gemm_xwt(const float* __restrict__ X, const float* __restrict__ W,
                         const float* __restrict__ bias, float* __restrict__ Y,
                         int Mn, int Nn, int Kn) {
    __shared__ float As[GKT][65];
    __shared__ float Bs[GKT][65];
    int t  = threadIdx.x;
    int tx = t & 15, ty = t >> 4;
    int bm = blockIdx.y * 64, bn = blockIdx.x * 64;
    float acc[4][4] = {};
    for (int k0 = 0; k0 < Kn; k0 += GKT) {
#pragma unroll
        for (int i = 0; i < (64*GKT)/256; i++) {
            int idx = t + i*256;
            int r = idx / GKT, k = idx % GKT;
            As[k][r] = X[(size_t)(bm+r)*Kn + k0 + k];
            Bs[k][r] = W[(size_t)(bn+r)*Kn + k0 + k];
        }
        __syncthreads();
#pragma unroll
        for (int k = 0; k < GKT; k++) {
            float a[4], bb[4];
#pragma unroll
            for (int i = 0; i < 4; i++) a[i]  = As[k][ty*4+i];
#pragma unroll
            for (int j = 0; j < 4; j++) bb[j] = Bs[k][tx*4+j];
#pragma unroll
            for (int i = 0; i < 4; i++)
#pragma unroll
                for (int j = 0; j < 4; j++)
                    acc[i][j] = fmaf(a[i], bb[j], acc[i][j]);
        }
        __syncthreads();
    }
#pragma unroll
    for (int i = 0; i < 4; i++) {
        int m = bm + ty*4 + i;
#pragma unroll
        for (int j = 0; j < 4; j++) {
            int n = bn + tx*4 + j;
            Y[(size_t)m*Nn + n] = acc[i][j] + bias[n];
        }
    }
}

// ---------------------------------------------------------------------------
// Attention: one block per (b, h, q-tile of 32). 256 threads.
// S = QK^T*scale + cluster ; softmax rows ; atomicAdd head-mean ; O = S @ V
// Dynamic smem layout (floats): S[32*1025] | Qs[32*65] | KVt[64*65]
// ---------------------------------------------------------------------------
__global__ void attn_kernel(const float* __restrict__ Q, const float* __restrict__ K,
                            const float* __restrict__ V, const float* __restrict__ CL,
                            float* __restrict__ AO, float* __restrict__ AM) {
    extern __shared__ float sm[];
    float* S   = sm;                 // 32*1025
    float* Qs  = S  + QTILE*SPAD;    // 32*65
    float* KVt = Qs + QTILE*65;      // 64*65

    int blk = blockIdx.x;
    int qt = blk & 31;
    int h  = (blk >> 5) & 15;
    int b  = blk >> 9;
    int q0 = qt * QTILE;
    int t  = threadIdx.x;
    const float scale = 0.125f;  // 1/sqrt(64)

    // load Q tile [32,64]
    for (int i = t; i < QTILE*HD; i += 256) {
        int qi = i >> 6, d = i & 63;
        Qs[qi*65 + d] = Q[((size_t)(b*NQ + q0 + qi))*DIM + h*HD + d];
    }

    int qi = t >> 3;       // 0..31
    int kb = t & 7;        // 0..7

    // ---- scores: S[qi][k] over all k ----
    for (int kt = 0; kt < NKV/KTILE; kt++) {
        __syncthreads();   // also covers Qs load at kt=0; KVt reuse after
        for (int i = t; i < KTILE*HD; i += 256) {
            int ki = i >> 6, d = i & 63;
            KVt[ki*65 + d] = K[((size_t)(b*NKV + kt*KTILE + ki))*DIM + h*HD + d];
        }
        __syncthreads();
        float acc[8] = {0,0,0,0,0,0,0,0};
#pragma unroll 4
        for (int d = 0; d < HD; d++) {
            float qv = Qs[qi*65 + d];
#pragma unroll
            for (int j = 0; j < 8; j++)
                acc[j] = fmaf(qv, KVt[(kb + 8*j)*65 + d], acc[j]);
        }
#pragma unroll
        for (int j = 0; j < 8; j++) {
            int k = kt*KTILE + kb + 8*j;
            S[qi*SPAD + k] = acc[j]*scale
                           + CL[((size_t)(b*NQ + q0 + qi))*NKV + k];
        }
    }
    __syncthreads();

    // ---- row softmax: warp w handles rows 4w..4w+3 ----
    int warp = t >> 5, lane = t & 31;
    for (int r = 0; r < 4; r++) {
        int row = warp*4 + r;
        float mx = -1e30f;
        for (int i = lane; i < NKV; i += 32) mx = fmaxf(mx, S[row*SPAD + i]);
#pragma unroll
        for (int o = 16; o; o >>= 1) mx = fmaxf(mx, __shfl_xor_sync(0xffffffffu, mx, o));
        float ssum = 0.0f;
        for (int i = lane; i < NKV; i += 32) {
            float e = __expf(S[row*SPAD + i] - mx);
            S[row*SPAD + i] = e;
            ssum += e;
        }
#pragma unroll
        for (int o = 16; o; o >>= 1) ssum += __shfl_xor_sync(0xffffffffu, ssum, o);
        float inv = 1.0f / ssum;
        for (int i = lane; i < NKV; i += 32) S[row*SPAD + i] *= inv;
    }
    __syncthreads();

    // ---- head-mean accumulation (atomic across 16 heads) ----
    for (int i = t; i < QTILE*NKV; i += 256) {
        int r = i >> 10, k = i & 1023;
        atomicAdd(&AM[((size_t)(b*NQ + q0 + r))*NKV + k], S[r*SPAD + k] * 0.0625f);
    }

    // ---- O = S @ V : thread owns (qi, 8 consecutive d) ----
    int dg = (t & 7) * 8;
    float oacc[8] = {0,0,0,0,0,0,0,0};
    for (int kt = 0; kt < NKV/KTILE; kt++) {
        __syncthreads();
        for (int i = t; i < KTILE*HD; i += 256) {
            int ki = i >> 6, d = i & 63;
            KVt[ki*65 + d] = V[((size_t)(b*NKV + kt*KTILE + ki))*DIM + h*HD + d];
        }
        __syncthreads();
#pragma unroll 4
        for (int ki = 0; ki < KTILE; ki++) {
            float w = S[qi*SPAD + kt*KTILE + ki];
#pragma unroll
            for (int j = 0; j < 8; j++)
                oacc[j] = fmaf(w, KVt[ki*65 + dg + j], oacc[j]);
        }
    }
#pragma unroll
    for (int j = 0; j < 8; j++)
        AO[((size_t)(b*NQ + q0 + qi))*DIM + h*HD + dg + j] = oacc[j];
}

// ---------------------------------------------------------------------------
extern "C" void kernel_launch(void* const* d_in, const int* in_sizes, int n_in,
                              void* d_out, int out_size) {
    const float* query = (const float*)d_in[0];
    const float* kv    = (const float*)d_in[1];
    const float* cl    = (const float*)d_in[2];
    const float* Wq    = (const float*)d_in[3];
    const float* bq    = (const float*)d_in[4];
    const float* Wk    = (const float*)d_in[5];
    const float* bk    = (const float*)d_in[6];
    const float* Wv    = (const float*)d_in[7];
    const float* bv    = (const float*)d_in[8];
    const float* Wo    = (const float*)d_in[9];
    const float* bo    = (const float*)d_in[10];

    float* out_uq = (float*)d_out;
    float* out_am = out_uq + (size_t)BB*NQ*NKV;

    float *gQ, *gK, *gV, *gAO;
    cudaGetSymbolAddress((void**)&gQ,  g_Q);
    cudaGetSymbolAddress((void**)&gK,  g_K);
    cudaGetSymbolAddress((void**)&gV,  g_V);
    cudaGetSymbolAddress((void**)&gAO, g_AO);

    // dynamic smem for attention
    const int smem_bytes = (QTILE*SPAD + QTILE*65 + KTILE*65) * (int)sizeof(float);
    cudaFuncSetAttribute(attn_kernel, cudaFuncAttributeMaxDynamicSharedMemorySize, smem_bytes);

    // zero attn_matrix region (it's accumulated atomically)
    zero_kernel<<<4096, 256>>>(out_am, BB*NQ*NKV);

    dim3 gg(DIM/64, M_TOT/64);   // (16, 128)
    gemm_xwt<<<gg, 256>>>(query, Wq, bq, gQ, M_TOT, DIM, DIM);
    gemm_xwt<<<gg, 256>>>(kv,    Wk, bk, gK, M_TOT, DIM, DIM);
    gemm_xwt<<<gg, 256>>>(kv,    Wv, bv, gV, M_TOT, DIM, DIM);

    attn_kernel<<<BB*NH*(NQ/QTILE), 256, smem_bytes>>>(gQ, gK, gV, cl, gAO, out_am);

    gemm_xwt<<<gg, 256>>>(gAO, Wo, bo, out_uq, M_TOT, DIM, DIM);
}

// round 3
// speedup vs baseline: 3.5953x; 3.5953x over previous
#include <cuda_runtime.h>
#include <cstdint>

#define BB 8
#define NQ 1024
#define NKV 1024
#define DIM 1024
#define NH 16
#define HD 64
#define M_TOT (BB*NQ)   // 8192
#define QTILE 32
#define KT2 128         // attention k-tile
#define SPAD 1028       // padded score row stride (floats, 16B-aligned rows)

// Scratch (allocation-free rule: __device__ globals)
__device__ float g_Q [M_TOT*DIM];
__device__ float g_K [M_TOT*DIM];
__device__ float g_V [M_TOT*DIM];
__device__ float g_AO[M_TOT*DIM];

// ---------------------------------------------------------------------------
__device__ __forceinline__ uint32_t f2tf32(float x) {
    uint32_t u;
    asm("cvt.rna.tf32.f32 %0, %1;" : "=r"(u) : "f"(x));
    return u;
}
__device__ __forceinline__ void mma_tf32(float& c0, float& c1, float& c2, float& c3,
                                         uint32_t a0, uint32_t a1, uint32_t a2, uint32_t a3,
                                         uint32_t b0, uint32_t b1) {
    asm volatile(
        "mma.sync.aligned.m16n8k8.row.col.f32.tf32.tf32.f32 "
        "{%0,%1,%2,%3}, {%4,%5,%6,%7}, {%8,%9}, {%0,%1,%2,%3};"
        : "+f"(c0), "+f"(c1), "+f"(c2), "+f"(c3)
        : "r"(a0), "r"(a1), "r"(a2), "r"(a3), "r"(b0), "r"(b1));
}
__device__ __forceinline__ void red_add_v4(float* p, float4 v) {
    asm volatile("red.global.add.v4.f32 [%0], {%1,%2,%3,%4};"
                 :: "l"(p), "f"(v.x), "f"(v.y), "f"(v.z), "f"(v.w) : "memory");
}

// ---------------------------------------------------------------------------
__global__ void zero_kernel(float4* __restrict__ p, int n4) {
    int i = blockIdx.x * blockDim.x + threadIdx.x;
    int stride = gridDim.x * blockDim.x;
    float4 z = {0.f, 0.f, 0.f, 0.f};
    for (; i < n4; i += stride) p[i] = z;
}

// ---------------------------------------------------------------------------
// tf32 mma.sync GEMM: Y[M,1024] = X[M,1024] @ W[1024,1024]^T + bias
// 128x128 CTA tile, 32-float k-chunks, double-buffered smem (stride 36),
// 8 warps: warp_m = wid&3 (32 rows), warp_n = wid>>2 (64 cols).
// ---------------------------------------------------------------------------
#define GST 36                       // smem row stride (floats)
#define GBUF (128*GST)               // floats per buffer per matrix
#define SMEM_G (512 + 4*GBUF*4)      // bias + 2xA + 2xB buffers (bytes)

__global__ __launch_bounds__(256)
void gemm_mma(const float* __restrict__ X, const float* __restrict__ W,
              const float* __restrict__ bias, float* __restrict__ Y) {
    extern __shared__ float sm[];
    float* bias_s = sm;              // 128 floats
    uint32_t* As = (uint32_t*)(sm + 128);
    uint32_t* Bs = As + 2*GBUF;

    int t = threadIdx.x, lane = t & 31, wid = t >> 5;
    int bm = blockIdx.y * 128, bn = blockIdx.x * 128;
    int wm = wid & 3, wn = wid >> 2;

    if (t < 128) bias_s[t] = bias[bn + t];

    // global load coords: 4 float4 per matrix per chunk
    int r0g = t >> 3;                // + 32*i
    int c4 = t & 7;

    float4 ra[4], rb[4];
    auto LDG = [&](int kt) {
#pragma unroll
        for (int i = 0; i < 4; i++) {
            int r = r0g + 32*i;
            ra[i] = *(const float4*)(X + (size_t)(bm + r)*DIM + kt*32 + c4*4);
            rb[i] = *(const float4*)(W + (size_t)(bn + r)*DIM + kt*32 + c4*4);
        }
    };
    auto STS = [&](int p) {
#pragma unroll
        for (int i = 0; i < 4; i++) {
            int r = r0g + 32*i;
            uint32_t* pa = As + p*GBUF + r*GST + c4*4;
            uint32_t* pb = Bs + p*GBUF + r*GST + c4*4;
            pa[0] = f2tf32(ra[i].x); pa[1] = f2tf32(ra[i].y);
            pa[2] = f2tf32(ra[i].z); pa[3] = f2tf32(ra[i].w);
            pb[0] = f2tf32(rb[i].x); pb[1] = f2tf32(rb[i].y);
            pb[2] = f2tf32(rb[i].z); pb[3] = f2tf32(rb[i].w);
        }
    };

    float c[2][8][4];
#pragma unroll
    for (int i = 0; i < 2; i++)
#pragma unroll
        for (int j = 0; j < 8; j++)
#pragma unroll
            for (int k = 0; k < 4; k++) c[i][j][k] = 0.f;

    LDG(0); STS(0);
    __syncthreads();

    int qr = lane >> 2, qc = lane & 3;
    for (int kt = 0; kt < DIM/32; kt++) {
        int p = kt & 1;
        if (kt < DIM/32 - 1) LDG(kt + 1);
        const uint32_t* Ab = As + p*GBUF;
        const uint32_t* Bb = Bs + p*GBUF;
#pragma unroll
        for (int s = 0; s < 4; s++) {
            int k0 = s*8;
            uint32_t af[2][4], bf[8][2];
#pragma unroll
            for (int tm = 0; tm < 2; tm++) {
                int row = wm*32 + tm*16 + qr;
                af[tm][0] = Ab[row*GST + k0 + qc];
                af[tm][1] = Ab[(row+8)*GST + k0 + qc];
                af[tm][2] = Ab[row*GST + k0 + 4 + qc];
                af[tm][3] = Ab[(row+8)*GST + k0 + 4 + qc];
            }
#pragma unroll
            for (int tn = 0; tn < 8; tn++) {
                int n = wn*64 + tn*8 + qr;
                bf[tn][0] = Bb[n*GST + k0 + qc];
                bf[tn][1] = Bb[n*GST + k0 + 4 + qc];
            }
#pragma unroll
            for (int tm = 0; tm < 2; tm++)
#pragma unroll
                for (int tn = 0; tn < 8; tn++)
                    mma_tf32(c[tm][tn][0], c[tm][tn][1], c[tm][tn][2], c[tm][tn][3],
                             af[tm][0], af[tm][1], af[tm][2], af[tm][3],
                             bf[tn][0], bf[tn][1]);
        }
        if (kt < DIM/32 - 1) STS(p ^ 1);
        __syncthreads();
    }

    // epilogue
#pragma unroll
    for (int tm = 0; tm < 2; tm++) {
        int row = bm + wm*32 + tm*16 + qr;
#pragma unroll
        for (int tn = 0; tn < 8; tn++) {
            int col = wn*64 + tn*8 + qc*2;
            float2 v0 = { c[tm][tn][0] + bias_s[col], c[tm][tn][1] + bias_s[col+1] };
            float2 v1 = { c[tm][tn][2] + bias_s[col], c[tm][tn][3] + bias_s[col+1] };
            *(float2*)(Y + (size_t)row*DIM + bn + col)     = v0;
            *(float2*)(Y + (size_t)(row+8)*DIM + bn + col) = v1;
        }
    }
}

// ---------------------------------------------------------------------------
// Attention: one block per (b, h, q-tile of 32). 256 threads.
// Register-blocked fp32: QK^T 4q x 4k per thread (K transposed in smem),
// AV 2q x 4d per thread (V row-major, float4 loads).
// smem: S[32*1028] | Qs[32*68] | KV[8704 floats, Kt or Vs]
// ---------------------------------------------------------------------------
__global__ void attn_kernel(const float* __restrict__ Q, const float* __restrict__ K,
                            const float* __restrict__ V, const float* __restrict__ CL,
                            float* __restrict__ AO, float* __restrict__ AM) {
    extern __shared__ float sm[];
    float* S  = sm;                  // 32*1028
    float* Qs = S + QTILE*SPAD;      // 32*68
    float* KV = Qs + QTILE*68;       // 8704 floats

    int blk = blockIdx.x;
    int qt = blk & 31;
    int h  = (blk >> 5) & 15;
    int b  = blk >> 9;
    int q0 = qt * QTILE;
    int t  = threadIdx.x;
    int lane = t & 31, wid = t >> 5;
    const float scale = 0.125f;

    // load Q tile [32,64] as float4
#pragma unroll
    for (int i = 0; i < 2; i++) {
        int f = t + i*256;
        int qi = f >> 4, d4 = f & 15;
        *(float4*)(Qs + qi*68 + d4*4) =
            *(const float4*)(Q + ((size_t)(b*NQ + q0 + qi))*DIM + h*HD + d4*4);
    }

    // ---- scores: per kt2, compute 32q x 128k with 4q x 4k per thread ----
    for (int kt = 0; kt < NKV/KT2; kt++) {
        int k0 = kt * KT2;
        __syncthreads();  // Kt buffer reuse (and Qs on first iter)
        // load K tile transposed: Kt[d][ki], stride 132
#pragma unroll
        for (int i = 0; i < 8; i++) {
            int f = t + i*256;
            int ki = f >> 4, d4 = f & 15;
            float4 v = *(const float4*)(K + ((size_t)(b*NKV + k0 + ki))*DIM + h*HD + d4*4);
            KV[(d4*4+0)*132 + ki] = v.x;
            KV[(d4*4+1)*132 + ki] = v.y;
            KV[(d4*4+2)*132 + ki] = v.z;
            KV[(d4*4+3)*132 + ki] = v.w;
        }
        __syncthreads();

        float acc[4][4] = {};
        const float* qrow = Qs + (wid*4)*68;
#pragma unroll 8
        for (int d = 0; d < HD; d++) {
            float4 kv = *(const float4*)(KV + d*132 + lane*4);
            float qv0 = qrow[d], qv1 = qrow[68 + d], qv2 = qrow[136 + d], qv3 = qrow[204 + d];
#pragma unroll
            for (int j = 0; j < 4; j++) {
                float kj = (&kv.x)[j];
                acc[0][j] = fmaf(qv0, kj, acc[0][j]);
                acc[1][j] = fmaf(qv1, kj, acc[1][j]);
                acc[2][j] = fmaf(qv2, kj, acc[2][j]);
                acc[3][j] = fmaf(qv3, kj, acc[3][j]);
            }
        }
#pragma unroll
        for (int i = 0; i < 4; i++) {
            int q = wid*4 + i;
            float4 cl4 = *(const float4*)(CL + ((size_t)(b*NQ + q0 + q))*NKV + k0 + lane*4);
            float4 sv;
            sv.x = acc[i][0]*scale + cl4.x;
            sv.y = acc[i][1]*scale + cl4.y;
            sv.z = acc[i][2]*scale + cl4.z;
            sv.w = acc[i][3]*scale + cl4.w;
            *(float4*)(S + q*SPAD + k0 + lane*4) = sv;
        }
    }
    __syncthreads();

    // ---- row softmax: warp w handles rows 4w..4w+3 ----
    for (int r = 0; r < 4; r++) {
        int row = wid*4 + r;
        float mx = -1e30f;
        for (int i = lane; i < NKV; i += 32) mx = fmaxf(mx, S[row*SPAD + i]);
#pragma unroll
        for (int o = 16; o; o >>= 1) mx = fmaxf(mx, __shfl_xor_sync(0xffffffffu, mx, o));
        float ssum = 0.0f;
        for (int i = lane; i < NKV; i += 32) {
            float e = __expf(S[row*SPAD + i] - mx);
            S[row*SPAD + i] = e;
            ssum += e;
        }
#pragma unroll
        for (int o = 16; o; o >>= 1) ssum += __shfl_xor_sync(0xffffffffu, ssum, o);
        float inv = 1.0f / ssum;
        for (int i = lane; i < NKV; i += 32) S[row*SPAD + i] *= inv;
    }
    __syncthreads();

    // ---- head-mean accumulation: vector red.global ----
    for (int i = t; i < QTILE*NKV/4; i += 256) {
        int r = i >> 8, k4 = i & 255;
        float4 w = *(float4*)(S + r*SPAD + k4*4);
        w.x *= 0.0625f; w.y *= 0.0625f; w.z *= 0.0625f; w.w *= 0.0625f;
        red_add_v4(AM + ((size_t)(b*NQ + q0 + r))*NKV + k4*4, w);
    }

    // ---- O = S @ V : thread owns 2q x 4d ----
    int ty2 = t >> 4;            // 0..15 -> q rows ty2*2, ty2*2+1
    int tx2 = t & 15;            // d = tx2*4..+3
    float oacc[2][4] = {};
    for (int kt = 0; kt < NKV/KT2; kt++) {
        int k0 = kt * KT2;
        __syncthreads();
        // load V tile [128][68]
#pragma unroll
        for (int i = 0; i < 8; i++) {
            int f = t + i*256;
            int ki = f >> 4, d4 = f & 15;
            *(float4*)(KV + ki*68 + d4*4) =
                *(const float4*)(V + ((size_t)(b*NKV + k0 + ki))*DIM + h*HD + d4*4);
        }
        __syncthreads();
        const float* s0 = S + (ty2*2)*SPAD + k0;
        const float* s1 = s0 + SPAD;
#pragma unroll 8
        for (int ki = 0; ki < KT2; ki++) {
            float4 vv = *(const float4*)(KV + ki*68 + tx2*4);
            float w0 = s0[ki], w1 = s1[ki];
#pragma unroll
            for (int j = 0; j < 4; j++) {
                float vj = (&vv.x)[j];
                oacc[0][j] = fmaf(w0, vj, oacc[0][j]);
                oacc[1][j] = fmaf(w1, vj, oacc[1][j]);
            }
        }
    }
#pragma unroll
    for (int r = 0; r < 2; r++) {
        float4 o4 = { oacc[r][0], oacc[r][1], oacc[r][2], oacc[r][3] };
        *(float4*)(AO + ((size_t)(b*NQ + q0 + ty2*2 + r))*DIM + h*HD + tx2*4) = o4;
    }
}

// ---------------------------------------------------------------------------
extern "C" void kernel_launch(void* const* d_in, const int* in_sizes, int n_in,
                              void* d_out, int out_size) {
    const float* query = (const float*)d_in[0];
    const float* kv    = (const float*)d_in[1];
    const float* cl    = (const float*)d_in[2];
    const float* Wq    = (const float*)d_in[3];
    const float* bq    = (const float*)d_in[4];
    const float* Wk    = (const float*)d_in[5];
    const float* bk    = (const float*)d_in[6];
    const float* Wv    = (const float*)d_in[7];
    const float* bv    = (const float*)d_in[8];
    const float* Wo    = (const float*)d_in[9];
    const float* bo    = (const float*)d_in[10];

    float* out_uq = (float*)d_out;
    float* out_am = out_uq + (size_t)BB*NQ*NKV;

    float *gQ, *gK, *gV, *gAO;
    cudaGetSymbolAddress((void**)&gQ,  g_Q);
    cudaGetSymbolAddress((void**)&gK,  g_K);
    cudaGetSymbolAddress((void**)&gV,  g_V);
    cudaGetSymbolAddress((void**)&gAO, g_AO);

    const int smem_attn = (QTILE*SPAD + QTILE*68 + 8704) * (int)sizeof(float);
    cudaFuncSetAttribute(attn_kernel, cudaFuncAttributeMaxDynamicSharedMemorySize, smem_attn);
    cudaFuncSetAttribute(gemm_mma, cudaFuncAttributeMaxDynamicSharedMemorySize, SMEM_G);

    zero_kernel<<<2048, 256>>>((float4*)out_am, BB*NQ*NKV/4);

    dim3 gg(DIM/128, M_TOT/128);   // (8, 64)
    gemm_mma<<<gg, 256, SMEM_G>>>(query, Wq, bq, gQ);
    gemm_mma<<<gg, 256, SMEM_G>>>(kv,    Wk, bk, gK);
    gemm_mma<<<gg, 256, SMEM_G>>>(kv,    Wv, bv, gV);

    attn_kernel<<<BB*NH*(NQ/QTILE), 256, smem_attn>>>(gQ, gK, gV, cl, gAO, out_am);

    gemm_mma<<<gg, 256, SMEM_G>>>(gAO, Wo, bo, out_uq);
}

// round 4
// speedup vs baseline: 5.2689x; 1.4655x over previous
#include <cuda_runtime.h>
#include <cstdint>

#define BB 8
#define NQ 1024
#define NKV 1024
#define DIM 1024
#define NH 16
#define HD 64
#define M_TOT (BB*NQ)   // 8192
#define QTILE 32
#define SPAD 1028       // S row stride (floats): 1028%32==4 -> conflict-free frag reads
#define QST 68          // Q smem stride (tf32)
#define KST 68          // K tile stride (tf32)
#define VST 72          // V tile stride (tf32)

// Scratch (allocation-free rule: __device__ globals)
__device__ float g_Q [M_TOT*DIM];
__device__ float g_K [M_TOT*DIM];
__device__ float g_V [M_TOT*DIM];
__device__ float g_AO[M_TOT*DIM];

// ---------------------------------------------------------------------------
__device__ __forceinline__ uint32_t f2tf32(float x) {
    uint32_t u;
    asm("cvt.rna.tf32.f32 %0, %1;" : "=r"(u) : "f"(x));
    return u;
}
__device__ __forceinline__ void mma_tf32(float& c0, float& c1, float& c2, float& c3,
                                         uint32_t a0, uint32_t a1, uint32_t a2, uint32_t a3,
                                         uint32_t b0, uint32_t b1) {
    asm volatile(
        "mma.sync.aligned.m16n8k8.row.col.f32.tf32.tf32.f32 "
        "{%0,%1,%2,%3}, {%4,%5,%6,%7}, {%8,%9}, {%0,%1,%2,%3};"
        : "+f"(c0), "+f"(c1), "+f"(c2), "+f"(c3)
        : "r"(a0), "r"(a1), "r"(a2), "r"(a3), "r"(b0), "r"(b1));
}
__device__ __forceinline__ void red_add_v4(float* p, float4 v) {
    asm volatile("red.global.add.v4.f32 [%0], {%1,%2,%3,%4};"
                 :: "l"(p), "f"(v.x), "f"(v.y), "f"(v.z), "f"(v.w) : "memory");
}

// ---------------------------------------------------------------------------
__global__ void zero_kernel(float4* __restrict__ p, int n4) {
    int i = blockIdx.x * blockDim.x + threadIdx.x;
    int stride = gridDim.x * blockDim.x;
    float4 z = {0.f, 0.f, 0.f, 0.f};
    for (; i < n4; i += stride) p[i] = z;
}

// ---------------------------------------------------------------------------
// tf32 mma.sync GEMM (unchanged from R3): Y = X @ W^T + bias
// ---------------------------------------------------------------------------
#define GST 36
#define GBUF (128*GST)
#define SMEM_G (512 + 4*GBUF*4)

__global__ __launch_bounds__(256)
void gemm_mma(const float* __restrict__ X, const float* __restrict__ W,
              const float* __restrict__ bias, float* __restrict__ Y) {
    extern __shared__ float sm[];
    float* bias_s = sm;
    uint32_t* As = (uint32_t*)(sm + 128);
    uint32_t* Bs = As + 2*GBUF;

    int t = threadIdx.x, lane = t & 31, wid = t >> 5;
    int bm = blockIdx.y * 128, bn = blockIdx.x * 128;
    int wm = wid & 3, wn = wid >> 2;

    if (t < 128) bias_s[t] = bias[bn + t];

    int r0g = t >> 3;
    int c4 = t & 7;

    float4 ra[4], rb[4];
    auto LDG = [&](int kt) {
#pragma unroll
        for (int i = 0; i < 4; i++) {
            int r = r0g + 32*i;
            ra[i] = *(const float4*)(X + (size_t)(bm + r)*DIM + kt*32 + c4*4);
            rb[i] = *(const float4*)(W + (size_t)(bn + r)*DIM + kt*32 + c4*4);
        }
    };
    auto STS = [&](int p) {
#pragma unroll
        for (int i = 0; i < 4; i++) {
            int r = r0g + 32*i;
            uint32_t* pa = As + p*GBUF + r*GST + c4*4;
            uint32_t* pb = Bs + p*GBUF + r*GST + c4*4;
            pa[0] = f2tf32(ra[i].x); pa[1] = f2tf32(ra[i].y);
            pa[2] = f2tf32(ra[i].z); pa[3] = f2tf32(ra[i].w);
            pb[0] = f2tf32(rb[i].x); pb[1] = f2tf32(rb[i].y);
            pb[2] = f2tf32(rb[i].z); pb[3] = f2tf32(rb[i].w);
        }
    };

    float c[2][8][4];
#pragma unroll
    for (int i = 0; i < 2; i++)
#pragma unroll
        for (int j = 0; j < 8; j++)
#pragma unroll
            for (int k = 0; k < 4; k++) c[i][j][k] = 0.f;

    LDG(0); STS(0);
    __syncthreads();

    int qr = lane >> 2, qc = lane & 3;
    for (int kt = 0; kt < DIM/32; kt++) {
        int p = kt & 1;
        if (kt < DIM/32 - 1) LDG(kt + 1);
        const uint32_t* Ab = As + p*GBUF;
        const uint32_t* Bb = Bs + p*GBUF;
#pragma unroll
        for (int s = 0; s < 4; s++) {
            int k0 = s*8;
            uint32_t af[2][4], bf[8][2];
#pragma unroll
            for (int tm = 0; tm < 2; tm++) {
                int row = wm*32 + tm*16 + qr;
                af[tm][0] = Ab[row*GST + k0 + qc];
                af[tm][1] = Ab[(row+8)*GST + k0 + qc];
                af[tm][2] = Ab[row*GST + k0 + 4 + qc];
                af[tm][3] = Ab[(row+8)*GST + k0 + 4 + qc];
            }
#pragma unroll
            for (int tn = 0; tn < 8; tn++) {
                int n = wn*64 + tn*8 + qr;
                bf[tn][0] = Bb[n*GST + k0 + qc];
                bf[tn][1] = Bb[n*GST + k0 + 4 + qc];
            }
#pragma unroll
            for (int tm = 0; tm < 2; tm++)
#pragma unroll
                for (int tn = 0; tn < 8; tn++)
                    mma_tf32(c[tm][tn][0], c[tm][tn][1], c[tm][tn][2], c[tm][tn][3],
                             af[tm][0], af[tm][1], af[tm][2], af[tm][3],
                             bf[tn][0], bf[tn][1]);
        }
        if (kt < DIM/32 - 1) STS(p ^ 1);
        __syncthreads();
    }

#pragma unroll
    for (int tm = 0; tm < 2; tm++) {
        int row = bm + wm*32 + tm*16 + qr;
#pragma unroll
        for (int tn = 0; tn < 8; tn++) {
            int col = wn*64 + tn*8 + qc*2;
            float2 v0 = { c[tm][tn][0] + bias_s[col], c[tm][tn][1] + bias_s[col+1] };
            float2 v1 = { c[tm][tn][2] + bias_s[col], c[tm][tn][3] + bias_s[col+1] };
            *(float2*)(Y + (size_t)row*DIM + bn + col)     = v0;
            *(float2*)(Y + (size_t)(row+8)*DIM + bn + col) = v1;
        }
    }
}

// ---------------------------------------------------------------------------
// Attention with tf32 mma.sync for QK^T and S@V.
// One block per (b, h, q-tile of 32). 256 threads = 8 warps.
// smem: S[32*SPAD] fp32 | Qs[32*QST] tf32 | KV[128*VST] tf32 (K or V tile)
// ---------------------------------------------------------------------------
__global__ __launch_bounds__(256)
void attn_kernel(const float* __restrict__ Q, const float* __restrict__ K,
                 const float* __restrict__ V, const float* __restrict__ CL,
                 float* __restrict__ AO, float* __restrict__ AM) {
    extern __shared__ float sm[];
    float* S = sm;                               // 32*SPAD fp32
    uint32_t* Qs = (uint32_t*)(S + QTILE*SPAD);  // 32*QST tf32
    uint32_t* KV = Qs + QTILE*QST;               // 128*VST tf32

    int blk = blockIdx.x;
    int qt = blk & 31;
    int h  = (blk >> 5) & 15;
    int b  = blk >> 9;
    int q0 = qt * QTILE;
    int t  = threadIdx.x;
    int lane = t & 31, wid = t >> 5;
    int qr = lane >> 2, qc = lane & 3;
    const float scale = 0.125f;

    // load Q tile [32,64] -> tf32 smem
#pragma unroll
    for (int i = 0; i < 2; i++) {
        int f = t + i*256;
        int qi = f >> 4, d4 = f & 15;
        float4 v = *(const float4*)(Q + ((size_t)(b*NQ + q0 + qi))*DIM + h*HD + d4*4);
        uint32_t* p = Qs + qi*QST + d4*4;
        p[0] = f2tf32(v.x); p[1] = f2tf32(v.y); p[2] = f2tf32(v.z); p[3] = f2tf32(v.w);
    }

    // ---- QK^T via mma: warp = (wm m16-half, wn n32-quarter of 128-chunk) ----
    int wm = wid & 1, wn = wid >> 1;
    int m0 = wm * 16;
    for (int kt = 0; kt < NKV/128; kt++) {
        __syncthreads();   // KV reuse; also covers Qs load at kt=0
        // K tile [128 x 64] -> tf32, stride KST
#pragma unroll
        for (int i = 0; i < 8; i++) {
            int f = t + i*256;
            int ki = f >> 4, d4 = f & 15;
            float4 v = *(const float4*)(K + ((size_t)(b*NKV + kt*128 + ki))*DIM + h*HD + d4*4);
            uint32_t* p = KV + ki*KST + d4*4;
            p[0] = f2tf32(v.x); p[1] = f2tf32(v.y); p[2] = f2tf32(v.z); p[3] = f2tf32(v.w);
        }
        __syncthreads();

        float c[4][4];
#pragma unroll
        for (int i = 0; i < 4; i++)
#pragma unroll
            for (int j = 0; j < 4; j++) c[i][j] = 0.f;

#pragma unroll
        for (int ks = 0; ks < 8; ks++) {
            int k0 = ks * 8;
            uint32_t a0 = Qs[(m0+qr)*QST + k0 + qc];
            uint32_t a1 = Qs[(m0+qr+8)*QST + k0 + qc];
            uint32_t a2 = Qs[(m0+qr)*QST + k0 + 4 + qc];
            uint32_t a3 = Qs[(m0+qr+8)*QST + k0 + 4 + qc];
#pragma unroll
            for (int nt = 0; nt < 4; nt++) {
                int n = wn*32 + nt*8 + qr;
                uint32_t b0 = KV[n*KST + k0 + qc];
                uint32_t b1 = KV[n*KST + k0 + 4 + qc];
                mma_tf32(c[nt][0], c[nt][1], c[nt][2], c[nt][3], a0, a1, a2, a3, b0, b1);
            }
        }
        // store S with scale + cluster
#pragma unroll
        for (int nt = 0; nt < 4; nt++) {
            int col = kt*128 + wn*32 + nt*8 + 2*qc;
            int r0 = m0 + qr, r1 = r0 + 8;
            float2 cl0 = *(const float2*)(CL + ((size_t)(b*NQ + q0 + r0))*NKV + col);
            float2 cl1 = *(const float2*)(CL + ((size_t)(b*NQ + q0 + r1))*NKV + col);
            *(float2*)(S + r0*SPAD + col) = make_float2(c[nt][0]*scale + cl0.x,
                                                        c[nt][1]*scale + cl0.y);
            *(float2*)(S + r1*SPAD + col) = make_float2(c[nt][2]*scale + cl1.x,
                                                        c[nt][3]*scale + cl1.y);
        }
    }
    __syncthreads();

    // ---- row softmax: warp w handles rows 4w..4w+3 ----
    for (int r = 0; r < 4; r++) {
        int row = wid*4 + r;
        float mx = -1e30f;
        for (int i = lane; i < NKV; i += 32) mx = fmaxf(mx, S[row*SPAD + i]);
#pragma unroll
        for (int o = 16; o; o >>= 1) mx = fmaxf(mx, __shfl_xor_sync(0xffffffffu, mx, o));
        float ssum = 0.0f;
        for (int i = lane; i < NKV; i += 32) {
            float e = __expf(S[row*SPAD + i] - mx);
            S[row*SPAD + i] = e;
            ssum += e;
        }
#pragma unroll
        for (int o = 16; o; o >>= 1) ssum += __shfl_xor_sync(0xffffffffu, ssum, o);
        float inv = 1.0f / ssum;
        for (int i = lane; i < NKV; i += 32) S[row*SPAD + i] *= inv;
    }
    __syncthreads();

    // ---- head-mean accumulation: vector red.global ----
    for (int i = t; i < QTILE*NKV/4; i += 256) {
        int r = i >> 8, k4 = i & 255;
        float4 w = *(float4*)(S + r*SPAD + k4*4);
        w.x *= 0.0625f; w.y *= 0.0625f; w.z *= 0.0625f; w.w *= 0.0625f;
        red_add_v4(AM + ((size_t)(b*NQ + q0 + r))*NKV + k4*4, w);
    }

    // ---- O = S @ V via mma: warp = (wm m16-half, wn n16-quarter of 64) ----
    float o[2][4];
#pragma unroll
    for (int i = 0; i < 2; i++)
#pragma unroll
        for (int j = 0; j < 4; j++) o[i][j] = 0.f;

    for (int kt = 0; kt < NKV/128; kt++) {
        __syncthreads();   // protects KV (prev-chunk frag reads / AM-red done before 1st)
        // V tile [128 x 64] -> tf32, stride VST
#pragma unroll
        for (int i = 0; i < 8; i++) {
            int f = t + i*256;
            int ki = f >> 4, d4 = f & 15;
            float4 v = *(const float4*)(V + ((size_t)(b*NKV + kt*128 + ki))*DIM + h*HD + d4*4);
            uint32_t* p = KV + ki*VST + d4*4;
            p[0] = f2tf32(v.x); p[1] = f2tf32(v.y); p[2] = f2tf32(v.z); p[3] = f2tf32(v.w);
        }
        __syncthreads();

#pragma unroll
        for (int ks = 0; ks < 16; ks++) {
            int k0 = kt*128 + ks*8;      // global k index base
            int kl = ks*8;               // local within tile
            uint32_t a0 = f2tf32(S[(m0+qr)*SPAD + k0 + qc]);
            uint32_t a1 = f2tf32(S[(m0+qr+8)*SPAD + k0 + qc]);
            uint32_t a2 = f2tf32(S[(m0+qr)*SPAD + k0 + 4 + qc]);
            uint32_t a3 = f2tf32(S[(m0+qr+8)*SPAD + k0 + 4 + qc]);
#pragma unroll
            for (int nt = 0; nt < 2; nt++) {
                int n = wn*16 + nt*8 + qr;           // d index
                uint32_t b0 = KV[(kl + qc)*VST + n];
                uint32_t b1 = KV[(kl + 4 + qc)*VST + n];
                mma_tf32(o[nt][0], o[nt][1], o[nt][2], o[nt][3], a0, a1, a2, a3, b0, b1);
            }
        }
    }
    // write AO
#pragma unroll
    for (int nt = 0; nt < 2; nt++) {
        int col = wn*16 + nt*8 + 2*qc;
        int r0 = m0 + qr, r1 = r0 + 8;
        *(float2*)(AO + ((size_t)(b*NQ + q0 + r0))*DIM + h*HD + col) =
            make_float2(o[nt][0], o[nt][1]);
        *(float2*)(AO + ((size_t)(b*NQ + q0 + r1))*DIM + h*HD + col) =
            make_float2(o[nt][2], o[nt][3]);
    }
}

// ---------------------------------------------------------------------------
extern "C" void kernel_launch(void* const* d_in, const int* in_sizes, int n_in,
                              void* d_out, int out_size) {
    const float* query = (const float*)d_in[0];
    const float* kv    = (const float*)d_in[1];
    const float* cl    = (const float*)d_in[2];
    const float* Wq    = (const float*)d_in[3];
    const float* bq    = (const float*)d_in[4];
    const float* Wk    = (const float*)d_in[5];
    const float* bk    = (const float*)d_in[6];
    const float* Wv    = (const float*)d_in[7];
    const float* bv    = (const float*)d_in[8];
    const float* Wo    = (const float*)d_in[9];
    const float* bo    = (const float*)d_in[10];

    float* out_uq = (float*)d_out;
    float* out_am = out_uq + (size_t)BB*NQ*NKV;

    float *gQ, *gK, *gV, *gAO;
    cudaGetSymbolAddress((void**)&gQ,  g_Q);
    cudaGetSymbolAddress((void**)&gK,  g_K);
    cudaGetSymbolAddress((void**)&gV,  g_V);
    cudaGetSymbolAddress((void**)&gAO, g_AO);

    const int smem_attn = (QTILE*SPAD + QTILE*QST + 128*VST) * (int)sizeof(float);
    cudaFuncSetAttribute(attn_kernel, cudaFuncAttributeMaxDynamicSharedMemorySize, smem_attn);
    cudaFuncSetAttribute(gemm_mma, cudaFuncAttributeMaxDynamicSharedMemorySize, SMEM_G);

    zero_kernel<<<2048, 256>>>((float4*)out_am, BB*NQ*NKV/4);

    dim3 gg(DIM/128, M_TOT/128);   // (8, 64)
    gemm_mma<<<gg, 256, SMEM_G>>>(query, Wq, bq, gQ);
    gemm_mma<<<gg, 256, SMEM_G>>>(kv,    Wk, bk, gK);
    gemm_mma<<<gg, 256, SMEM_G>>>(kv,    Wv, bv, gV);

    attn_kernel<<<BB*NH*(NQ/QTILE), 256, smem_attn>>>(gQ, gK, gV, cl, gAO, out_am);

    gemm_mma<<<gg, 256, SMEM_G>>>(gAO, Wo, bo, out_uq);
}

// round 5
// speedup vs baseline: 5.8569x; 1.1116x over previous
#include <cuda_runtime.h>
#include <cstdint>

#define BB 8
#define NQ 1024
#define NKV 1024
#define DIM 1024
#define NH 16
#define HD 64
#define M_TOT (BB*NQ)   // 8192
#define QTILE 32
#define SPAD 1028       // S row stride (floats): %32==4 -> conflict-free frag reads
#define QST 68          // Q smem stride (tf32)
#define KST 68          // K tile stride (tf32)
#define VST 72          // V tile stride (tf32)

// Scratch (allocation-free rule: __device__ globals)
__device__ float g_Q [M_TOT*DIM];
__device__ float g_K [M_TOT*DIM];
__device__ float g_V [M_TOT*DIM];
__device__ float g_AO[M_TOT*DIM];

// ---------------------------------------------------------------------------
__device__ __forceinline__ uint32_t f2tf32(float x) {
    uint32_t u;
    asm("cvt.rna.tf32.f32 %0, %1;" : "=r"(u) : "f"(x));
    return u;
}
__device__ __forceinline__ void mma_tf32(float& c0, float& c1, float& c2, float& c3,
                                         uint32_t a0, uint32_t a1, uint32_t a2, uint32_t a3,
                                         uint32_t b0, uint32_t b1) {
    asm volatile(
        "mma.sync.aligned.m16n8k8.row.col.f32.tf32.tf32.f32 "
        "{%0,%1,%2,%3}, {%4,%5,%6,%7}, {%8,%9}, {%0,%1,%2,%3};"
        : "+f"(c0), "+f"(c1), "+f"(c2), "+f"(c3)
        : "r"(a0), "r"(a1), "r"(a2), "r"(a3), "r"(b0), "r"(b1));
}
__device__ __forceinline__ void red_add_v4(float* p, float4 v) {
    asm volatile("red.global.add.v4.f32 [%0], {%1,%2,%3,%4};"
                 :: "l"(p), "f"(v.x), "f"(v.y), "f"(v.z), "f"(v.w) : "memory");
}

// ---------------------------------------------------------------------------
__global__ void zero_kernel(float4* __restrict__ p, int n4) {
    int i = blockIdx.x * blockDim.x + threadIdx.x;
    int stride = gridDim.x * blockDim.x;
    float4 z = {0.f, 0.f, 0.f, 0.f};
    for (; i < n4; i += stride) p[i] = z;
}

// ---------------------------------------------------------------------------
// tf32 mma.sync GEMM: Y = X @ W^T + bias  (128x128 tile, double-buffered)
// ---------------------------------------------------------------------------
#define GST 36
#define GBUF (128*GST)
#define SMEM_G (512 + 4*GBUF*4)

__global__ __launch_bounds__(256, 2)
void gemm_mma(const float* __restrict__ X, const float* __restrict__ W,
              const float* __restrict__ bias, float* __restrict__ Y) {
    extern __shared__ float sm[];
    float* bias_s = sm;
    uint32_t* As = (uint32_t*)(sm + 128);
    uint32_t* Bs = As + 2*GBUF;

    int t = threadIdx.x, lane = t & 31, wid = t >> 5;
    int bm = blockIdx.y * 128, bn = blockIdx.x * 128;
    int wm = wid & 3, wn = wid >> 2;

    if (t < 128) bias_s[t] = bias[bn + t];

    int r0g = t >> 3;
    int c4 = t & 7;

    float4 ra[4], rb[4];
    auto LDG = [&](int kt) {
#pragma unroll
        for (int i = 0; i < 4; i++) {
            int r = r0g + 32*i;
            ra[i] = *(const float4*)(X + (size_t)(bm + r)*DIM + kt*32 + c4*4);
            rb[i] = *(const float4*)(W + (size_t)(bn + r)*DIM + kt*32 + c4*4);
        }
    };
    auto STS = [&](int p) {
#pragma unroll
        for (int i = 0; i < 4; i++) {
            int r = r0g + 32*i;
            uint32_t* pa = As + p*GBUF + r*GST + c4*4;
            uint32_t* pb = Bs + p*GBUF + r*GST + c4*4;
            pa[0] = f2tf32(ra[i].x); pa[1] = f2tf32(ra[i].y);
            pa[2] = f2tf32(ra[i].z); pa[3] = f2tf32(ra[i].w);
            pb[0] = f2tf32(rb[i].x); pb[1] = f2tf32(rb[i].y);
            pb[2] = f2tf32(rb[i].z); pb[3] = f2tf32(rb[i].w);
        }
    };

    float c[2][8][4];
#pragma unroll
    for (int i = 0; i < 2; i++)
#pragma unroll
        for (int j = 0; j < 8; j++)
#pragma unroll
            for (int k = 0; k < 4; k++) c[i][j][k] = 0.f;

    LDG(0); STS(0);
    __syncthreads();

    int qr = lane >> 2, qc = lane & 3;
    for (int kt = 0; kt < DIM/32; kt++) {
        int p = kt & 1;
        if (kt < DIM/32 - 1) LDG(kt + 1);
        const uint32_t* Ab = As + p*GBUF;
        const uint32_t* Bb = Bs + p*GBUF;
#pragma unroll
        for (int s = 0; s < 4; s++) {
            int k0 = s*8;
            uint32_t af[2][4], bf[8][2];
#pragma unroll
            for (int tm = 0; tm < 2; tm++) {
                int row = wm*32 + tm*16 + qr;
                af[tm][0] = Ab[row*GST + k0 + qc];
                af[tm][1] = Ab[(row+8)*GST + k0 + qc];
                af[tm][2] = Ab[row*GST + k0 + 4 + qc];
                af[tm][3] = Ab[(row+8)*GST + k0 + 4 + qc];
            }
#pragma unroll
            for (int tn = 0; tn < 8; tn++) {
                int n = wn*64 + tn*8 + qr;
                bf[tn][0] = Bb[n*GST + k0 + qc];
                bf[tn][1] = Bb[n*GST + k0 + 4 + qc];
            }
#pragma unroll
            for (int tm = 0; tm < 2; tm++)
#pragma unroll
                for (int tn = 0; tn < 8; tn++)
                    mma_tf32(c[tm][tn][0], c[tm][tn][1], c[tm][tn][2], c[tm][tn][3],
                             af[tm][0], af[tm][1], af[tm][2], af[tm][3],
                             bf[tn][0], bf[tn][1]);
        }
        if (kt < DIM/32 - 1) STS(p ^ 1);
        __syncthreads();
    }

#pragma unroll
    for (int tm = 0; tm < 2; tm++) {
        int row = bm + wm*32 + tm*16 + qr;
#pragma unroll
        for (int tn = 0; tn < 8; tn++) {
            int col = wn*64 + tn*8 + qc*2;
            float2 v0 = { c[tm][tn][0] + bias_s[col], c[tm][tn][1] + bias_s[col+1] };
            float2 v1 = { c[tm][tn][2] + bias_s[col], c[tm][tn][3] + bias_s[col+1] };
            *(float2*)(Y + (size_t)row*DIM + bn + col)     = v0;
            *(float2*)(Y + (size_t)(row+8)*DIM + bn + col) = v1;
        }
    }
}

// ---------------------------------------------------------------------------
// Attention, 512 threads = 16 warps per block (b, h, 32-q tile).
// QK^T: warp tile m16 x n16 (2 x 8 warps over 32 x 128 chunk)
// AV:   warp tile m16 x n8  (2 x 8 warps over 32 x 64 output)
// smem: S[32*SPAD] fp32 | Qs[32*QST] tf32 | KV[128*VST] tf32
// ---------------------------------------------------------------------------
__global__ __launch_bounds__(512)
void attn_kernel(const float* __restrict__ Q, const float* __restrict__ K,
                 const float* __restrict__ V, const float* __restrict__ CL,
                 float* __restrict__ AO, float* __restrict__ AM) {
    extern __shared__ float sm[];
    float* S = sm;                               // 32*SPAD fp32
    uint32_t* Qs = (uint32_t*)(S + QTILE*SPAD);  // 32*QST tf32
    uint32_t* KV = Qs + QTILE*QST;               // 128*VST tf32

    int blk = blockIdx.x;
    int qt = blk & 31;
    int h  = (blk >> 5) & 15;
    int b  = blk >> 9;
    int q0 = qt * QTILE;
    int t  = threadIdx.x;
    int lane = t & 31, wid = t >> 5;
    int qr = lane >> 2, qc = lane & 3;
    int wm = wid & 1, wn = wid >> 1;     // wm: m16 half, wn: 0..7
    int m0 = wm * 16;
    const float scale = 0.125f;

    // load Q tile [32,64] -> tf32 smem (512 float4 slots, one per thread)
    {
        int qi = t >> 4, d4 = t & 15;
        float4 v = *(const float4*)(Q + ((size_t)(b*NQ + q0 + qi))*DIM + h*HD + d4*4);
        uint32_t* p = Qs + qi*QST + d4*4;
        p[0] = f2tf32(v.x); p[1] = f2tf32(v.y); p[2] = f2tf32(v.z); p[3] = f2tf32(v.w);
    }

    // ---- QK^T ----
    for (int kt = 0; kt < NKV/128; kt++) {
        __syncthreads();   // KV reuse; also covers Qs load at kt=0
        // K tile [128 x 64] -> tf32, stride KST
#pragma unroll
        for (int i = 0; i < 4; i++) {
            int f = t + i*512;
            int ki = f >> 4, d4 = f & 15;
            float4 v = *(const float4*)(K + ((size_t)(b*NKV + kt*128 + ki))*DIM + h*HD + d4*4);
            uint32_t* p = KV + ki*KST + d4*4;
            p[0] = f2tf32(v.x); p[1] = f2tf32(v.y); p[2] = f2tf32(v.z); p[3] = f2tf32(v.w);
        }
        __syncthreads();

        float c[2][4];
#pragma unroll
        for (int i = 0; i < 2; i++)
#pragma unroll
            for (int j = 0; j < 4; j++) c[i][j] = 0.f;

#pragma unroll
        for (int ks = 0; ks < 8; ks++) {
            int k0 = ks * 8;
            uint32_t a0 = Qs[(m0+qr)*QST + k0 + qc];
            uint32_t a1 = Qs[(m0+qr+8)*QST + k0 + qc];
            uint32_t a2 = Qs[(m0+qr)*QST + k0 + 4 + qc];
            uint32_t a3 = Qs[(m0+qr+8)*QST + k0 + 4 + qc];
#pragma unroll
            for (int nt = 0; nt < 2; nt++) {
                int n = wn*16 + nt*8 + qr;
                uint32_t b0 = KV[n*KST + k0 + qc];
                uint32_t b1 = KV[n*KST + k0 + 4 + qc];
                mma_tf32(c[nt][0], c[nt][1], c[nt][2], c[nt][3], a0, a1, a2, a3, b0, b1);
            }
        }
        // store S with scale + cluster
#pragma unroll
        for (int nt = 0; nt < 2; nt++) {
            int col = kt*128 + wn*16 + nt*8 + 2*qc;
            int r0 = m0 + qr, r1 = r0 + 8;
            float2 cl0 = *(const float2*)(CL + ((size_t)(b*NQ + q0 + r0))*NKV + col);
            float2 cl1 = *(const float2*)(CL + ((size_t)(b*NQ + q0 + r1))*NKV + col);
            *(float2*)(S + r0*SPAD + col) = make_float2(c[nt][0]*scale + cl0.x,
                                                        c[nt][1]*scale + cl0.y);
            *(float2*)(S + r1*SPAD + col) = make_float2(c[nt][2]*scale + cl1.x,
                                                        c[nt][3]*scale + cl1.y);
        }
    }
    __syncthreads();

    // ---- row softmax: warp w handles rows 2w, 2w+1 ----
#pragma unroll
    for (int r = 0; r < 2; r++) {
        int row = wid*2 + r;
        float mx = -1e30f;
        for (int i = lane; i < NKV; i += 32) mx = fmaxf(mx, S[row*SPAD + i]);
#pragma unroll
        for (int o = 16; o; o >>= 1) mx = fmaxf(mx, __shfl_xor_sync(0xffffffffu, mx, o));
        float ssum = 0.0f;
        for (int i = lane; i < NKV; i += 32) {
            float e = __expf(S[row*SPAD + i] - mx);
            S[row*SPAD + i] = e;
            ssum += e;
        }
#pragma unroll
        for (int o = 16; o; o >>= 1) ssum += __shfl_xor_sync(0xffffffffu, ssum, o);
        float inv = 1.0f / ssum;
        for (int i = lane; i < NKV; i += 32) S[row*SPAD + i] *= inv;
    }
    __syncthreads();

    // ---- head-mean accumulation: vector red.global ----
    for (int i = t; i < QTILE*NKV/4; i += 512) {
        int r = i >> 8, k4 = i & 255;
        float4 w = *(float4*)(S + r*SPAD + k4*4);
        w.x *= 0.0625f; w.y *= 0.0625f; w.z *= 0.0625f; w.w *= 0.0625f;
        red_add_v4(AM + ((size_t)(b*NQ + q0 + r))*NKV + k4*4, w);
    }

    // ---- O = S @ V : warp tile m16 x n8 (wn picks d-octet) ----
    float o[4] = {0.f, 0.f, 0.f, 0.f};
    int n0 = wn * 8;

    for (int kt = 0; kt < NKV/128; kt++) {
        __syncthreads();   // protects KV
        // V tile [128 x 64] -> tf32, stride VST
#pragma unroll
        for (int i = 0; i < 4; i++) {
            int f = t + i*512;
            int ki = f >> 4, d4 = f & 15;
            float4 v = *(const float4*)(V + ((size_t)(b*NKV + kt*128 + ki))*DIM + h*HD + d4*4);
            uint32_t* p = KV + ki*VST + d4*4;
            p[0] = f2tf32(v.x); p[1] = f2tf32(v.y); p[2] = f2tf32(v.z); p[3] = f2tf32(v.w);
        }
        __syncthreads();

#pragma unroll
        for (int ks = 0; ks < 16; ks++) {
            int k0 = kt*128 + ks*8;
            int kl = ks*8;
            uint32_t a0 = f2tf32(S[(m0+qr)*SPAD + k0 + qc]);
            uint32_t a1 = f2tf32(S[(m0+qr+8)*SPAD + k0 + qc]);
            uint32_t a2 = f2tf32(S[(m0+qr)*SPAD + k0 + 4 + qc]);
            uint32_t a3 = f2tf32(S[(m0+qr+8)*SPAD + k0 + 4 + qc]);
            uint32_t b0 = KV[(kl + qc)*VST + n0 + qr];
            uint32_t b1 = KV[(kl + 4 + qc)*VST + n0 + qr];
            mma_tf32(o[0], o[1], o[2], o[3], a0, a1, a2, a3, b0, b1);
        }
    }
    // write AO
    {
        int col = n0 + 2*qc;
        int r0 = m0 + qr, r1 = r0 + 8;
        *(float2*)(AO + ((size_t)(b*NQ + q0 + r0))*DIM + h*HD + col) = make_float2(o[0], o[1]);
        *(float2*)(AO + ((size_t)(b*NQ + q0 + r1))*DIM + h*HD + col) = make_float2(o[2], o[3]);
    }
}

// ---------------------------------------------------------------------------
extern "C" void kernel_launch(void* const* d_in, const int* in_sizes, int n_in,
                              void* d_out, int out_size) {
    const float* query = (const float*)d_in[0];
    const float* kv    = (const float*)d_in[1];
    const float* cl    = (const float*)d_in[2];
    const float* Wq    = (const float*)d_in[3];
    const float* bq    = (const float*)d_in[4];
    const float* Wk    = (const float*)d_in[5];
    const float* bk    = (const float*)d_in[6];
    const float* Wv    = (const float*)d_in[7];
    const float* bv    = (const float*)d_in[8];
    const float* Wo    = (const float*)d_in[9];
    const float* bo    = (const float*)d_in[10];

    float* out_uq = (float*)d_out;
    float* out_am = out_uq + (size_t)BB*NQ*NKV;

    float *gQ, *gK, *gV, *gAO;
    cudaGetSymbolAddress((void**)&gQ,  g_Q);
    cudaGetSymbolAddress((void**)&gK,  g_K);
    cudaGetSymbolAddress((void**)&gV,  g_V);
    cudaGetSymbolAddress((void**)&gAO, g_AO);

    const int smem_attn = (QTILE*SPAD + QTILE*QST + 128*VST) * (int)sizeof(float);
    cudaFuncSetAttribute(attn_kernel, cudaFuncAttributeMaxDynamicSharedMemorySize, smem_attn);
    cudaFuncSetAttribute(gemm_mma, cudaFuncAttributeMaxDynamicSharedMemorySize, SMEM_G);

    zero_kernel<<<2048, 256>>>((float4*)out_am, BB*NQ*NKV/4);

    dim3 gg(DIM/128, M_TOT/128);   // (8, 64)
    gemm_mma<<<gg, 256, SMEM_G>>>(query, Wq, bq, gQ);
    gemm_mma<<<gg, 256, SMEM_G>>>(kv,    Wk, bk, gK);
    gemm_mma<<<gg, 256, SMEM_G>>>(kv,    Wv, bv, gV);

    attn_kernel<<<BB*NH*(NQ/QTILE), 512, smem_attn>>>(gQ, gK, gV, cl, gAO, out_am);

    gemm_mma<<<gg, 256, SMEM_G>>>(gAO, Wo, bo, out_uq);
}

// round 6
// speedup vs baseline: 6.0270x; 1.0290x over previous
#include <cuda_runtime.h>
#include <cstdint>

#define BB 8
#define NQ 1024
#define NKV 1024
#define DIM 1024
#define NH 16
#define HD 64
#define M_TOT (BB*NQ)   // 8192
#define QTILE 32
#define SPAD 1028       // S row stride (floats): %32==4 -> conflict-free frag reads
#define QST 68          // Q smem stride (tf32)
#define KST 68          // K tile stride (tf32)
#define VST 72          // V tile stride (tf32)
#define KVBUF (128*VST) // one K/V buffer (tf32 words)

// Scratch (allocation-free rule: __device__ globals)
__device__ float g_Q [M_TOT*DIM];
__device__ float g_K [M_TOT*DIM];
__device__ float g_V [M_TOT*DIM];
__device__ float g_AO[M_TOT*DIM];

// ---------------------------------------------------------------------------
__device__ __forceinline__ uint32_t f2tf32(float x) {
    uint32_t u;
    asm("cvt.rna.tf32.f32 %0, %1;" : "=r"(u) : "f"(x));
    return u;
}
__device__ __forceinline__ void mma_tf32(float& c0, float& c1, float& c2, float& c3,
                                         uint32_t a0, uint32_t a1, uint32_t a2, uint32_t a3,
                                         uint32_t b0, uint32_t b1) {
    asm volatile(
        "mma.sync.aligned.m16n8k8.row.col.f32.tf32.tf32.f32 "
        "{%0,%1,%2,%3}, {%4,%5,%6,%7}, {%8,%9}, {%0,%1,%2,%3};"
        : "+f"(c0), "+f"(c1), "+f"(c2), "+f"(c3)
        : "r"(a0), "r"(a1), "r"(a2), "r"(a3), "r"(b0), "r"(b1));
}
__device__ __forceinline__ void red_add_v4(float* p, float4 v) {
    asm volatile("red.global.add.v4.f32 [%0], {%1,%2,%3,%4};"
                 :: "l"(p), "f"(v.x), "f"(v.y), "f"(v.z), "f"(v.w) : "memory");
}

// ---------------------------------------------------------------------------
__global__ void zero_kernel(float4* __restrict__ p, int n4) {
    int i = blockIdx.x * blockDim.x + threadIdx.x;
    int stride = gridDim.x * blockDim.x;
    float4 z = {0.f, 0.f, 0.f, 0.f};
    for (; i < n4; i += stride) p[i] = z;
}

// ---------------------------------------------------------------------------
// tf32 mma.sync GEMM: Y = X @ W^T + bias  (128x128 tile, double-buffered)
// ---------------------------------------------------------------------------
#define GST 36
#define GBUF (128*GST)
#define SMEM_G (512 + 4*GBUF*4)

__global__ __launch_bounds__(256, 2)
void gemm_mma(const float* __restrict__ X, const float* __restrict__ W,
              const float* __restrict__ bias, float* __restrict__ Y) {
    extern __shared__ float sm[];
    float* bias_s = sm;
    uint32_t* As = (uint32_t*)(sm + 128);
    uint32_t* Bs = As + 2*GBUF;

    int t = threadIdx.x, lane = t & 31, wid = t >> 5;
    int bm = blockIdx.y * 128, bn = blockIdx.x * 128;
    int wm = wid & 3, wn = wid >> 2;

    if (t < 128) bias_s[t] = bias[bn + t];

    int r0g = t >> 3;
    int c4 = t & 7;

    float4 ra[4], rb[4];
    auto LDG = [&](int kt) {
#pragma unroll
        for (int i = 0; i < 4; i++) {
            int r = r0g + 32*i;
            ra[i] = *(const float4*)(X + (size_t)(bm + r)*DIM + kt*32 + c4*4);
            rb[i] = *(const float4*)(W + (size_t)(bn + r)*DIM + kt*32 + c4*4);
        }
    };
    auto STS = [&](int p) {
#pragma unroll
        for (int i = 0; i < 4; i++) {
            int r = r0g + 32*i;
            uint32_t* pa = As + p*GBUF + r*GST + c4*4;
            uint32_t* pb = Bs + p*GBUF + r*GST + c4*4;
            pa[0] = f2tf32(ra[i].x); pa[1] = f2tf32(ra[i].y);
            pa[2] = f2tf32(ra[i].z); pa[3] = f2tf32(ra[i].w);
            pb[0] = f2tf32(rb[i].x); pb[1] = f2tf32(rb[i].y);
            pb[2] = f2tf32(rb[i].z); pb[3] = f2tf32(rb[i].w);
        }
    };

    float c[2][8][4];
#pragma unroll
    for (int i = 0; i < 2; i++)
#pragma unroll
        for (int j = 0; j < 8; j++)
#pragma unroll
            for (int k = 0; k < 4; k++) c[i][j][k] = 0.f;

    LDG(0); STS(0);
    __syncthreads();

    int qr = lane >> 2, qc = lane & 3;
    for (int kt = 0; kt < DIM/32; kt++) {
        int p = kt & 1;
        if (kt < DIM/32 - 1) LDG(kt + 1);
        const uint32_t* Ab = As + p*GBUF;
        const uint32_t* Bb = Bs + p*GBUF;
#pragma unroll
        for (int s = 0; s < 4; s++) {
            int k0 = s*8;
            uint32_t af[2][4], bf[8][2];
#pragma unroll
            for (int tm = 0; tm < 2; tm++) {
                int row = wm*32 + tm*16 + qr;
                af[tm][0] = Ab[row*GST + k0 + qc];
                af[tm][1] = Ab[(row+8)*GST + k0 + qc];
                af[tm][2] = Ab[row*GST + k0 + 4 + qc];
                af[tm][3] = Ab[(row+8)*GST + k0 + 4 + qc];
            }
#pragma unroll
            for (int tn = 0; tn < 8; tn++) {
                int n = wn*64 + tn*8 + qr;
                bf[tn][0] = Bb[n*GST + k0 + qc];
                bf[tn][1] = Bb[n*GST + k0 + 4 + qc];
            }
#pragma unroll
            for (int tm = 0; tm < 2; tm++)
#pragma unroll
                for (int tn = 0; tn < 8; tn++)
                    mma_tf32(c[tm][tn][0], c[tm][tn][1], c[tm][tn][2], c[tm][tn][3],
                             af[tm][0], af[tm][1], af[tm][2], af[tm][3],
                             bf[tn][0], bf[tn][1]);
        }
        if (kt < DIM/32 - 1) STS(p ^ 1);
        __syncthreads();
    }

#pragma unroll
    for (int tm = 0; tm < 2; tm++) {
        int row = bm + wm*32 + tm*16 + qr;
#pragma unroll
        for (int tn = 0; tn < 8; tn++) {
            int col = wn*64 + tn*8 + qc*2;
            float2 v0 = { c[tm][tn][0] + bias_s[col], c[tm][tn][1] + bias_s[col+1] };
            float2 v1 = { c[tm][tn][2] + bias_s[col], c[tm][tn][3] + bias_s[col+1] };
            *(float2*)(Y + (size_t)row*DIM + bn + col)     = v0;
            *(float2*)(Y + (size_t)(row+8)*DIM + bn + col) = v1;
        }
    }
}

// ---------------------------------------------------------------------------
// Attention, 512 threads = 16 warps, double-buffered K/V, fused normalization.
// QK^T: warp tile m16 x n16; AV: warp tile m16 x n8.
// smem: S[32*SPAD] fp32 (unnormalized exp after softmax) | Qs | KV[2 bufs] | inv[32]
// ---------------------------------------------------------------------------
__global__ __launch_bounds__(512)
void attn_kernel(const float* __restrict__ Q, const float* __restrict__ K,
                 const float* __restrict__ V, const float* __restrict__ CL,
                 float* __restrict__ AO, float* __restrict__ AM) {
    extern __shared__ float sm[];
    float* S = sm;                               // 32*SPAD fp32
    uint32_t* Qs = (uint32_t*)(S + QTILE*SPAD);  // 32*QST tf32
    uint32_t* KV = Qs + QTILE*QST;               // 2 * KVBUF tf32
    float* invs = (float*)(KV + 2*KVBUF);        // 32 floats

    int blk = blockIdx.x;
    int qt = blk & 31;
    int h  = (blk >> 5) & 15;
    int b  = blk >> 9;
    int q0 = qt * QTILE;
    int t  = threadIdx.x;
    int lane = t & 31, wid = t >> 5;
    int qr = lane >> 2, qc = lane & 3;
    int wm = wid & 1, wn = wid >> 1;     // wm: m16 half, wn: 0..7
    int m0 = wm * 16;
    const float scale = 0.125f;

    int ldr = t >> 4;        // row slot for KV loads (+128 per i-step... see below)
    int ldd = t & 15;        // d4

    const float* Kbase = K + ((size_t)(b*NKV))*DIM + h*HD;
    const float* Vbase = V + ((size_t)(b*NKV))*DIM + h*HD;

    float4 rk[4];
    auto LDG_K = [&](int kt) {
#pragma unroll
        for (int i = 0; i < 4; i++) {
            int ki = ldr + i*32;
            rk[i] = *(const float4*)(Kbase + (size_t)(kt*128 + ki)*DIM + ldd*4);
        }
    };
    auto STS_K = [&](int p) {
#pragma unroll
        for (int i = 0; i < 4; i++) {
            int ki = ldr + i*32;
            uint32_t* q = KV + p*KVBUF + ki*KST + ldd*4;
            q[0] = f2tf32(rk[i].x); q[1] = f2tf32(rk[i].y);
            q[2] = f2tf32(rk[i].z); q[3] = f2tf32(rk[i].w);
        }
    };
    auto LDG_V = [&](int kt) {
#pragma unroll
        for (int i = 0; i < 4; i++) {
            int ki = ldr + i*32;
            rk[i] = *(const float4*)(Vbase + (size_t)(kt*128 + ki)*DIM + ldd*4);
        }
    };
    auto STS_V = [&](int p) {
#pragma unroll
        for (int i = 0; i < 4; i++) {
            int ki = ldr + i*32;
            uint32_t* q = KV + p*KVBUF + ki*VST + ldd*4;
            q[0] = f2tf32(rk[i].x); q[1] = f2tf32(rk[i].y);
            q[2] = f2tf32(rk[i].z); q[3] = f2tf32(rk[i].w);
        }
    };

    // load Q tile [32,64] -> tf32 smem (512 float4 slots)
    {
        int qi = t >> 4, d4 = t & 15;
        float4 v = *(const float4*)(Q + ((size_t)(b*NQ + q0 + qi))*DIM + h*HD + d4*4);
        uint32_t* p = Qs + qi*QST + d4*4;
        p[0] = f2tf32(v.x); p[1] = f2tf32(v.y); p[2] = f2tf32(v.z); p[3] = f2tf32(v.w);
    }
    LDG_K(0); STS_K(0);
    __syncthreads();

    // ---- QK^T, double-buffered ----
    const float* CLr0 = CL + ((size_t)(b*NQ + q0 + m0 + qr))*NKV;
    const float* CLr1 = CLr0 + (size_t)8*NKV;
    for (int kt = 0; kt < NKV/128; kt++) {
        int p = kt & 1;
        if (kt < 7) LDG_K(kt + 1);
        // prefetch CL for this chunk
        float2 cl0[2], cl1[2];
#pragma unroll
        for (int nt = 0; nt < 2; nt++) {
            int col = kt*128 + wn*16 + nt*8 + 2*qc;
            cl0[nt] = *(const float2*)(CLr0 + col);
            cl1[nt] = *(const float2*)(CLr1 + col);
        }

        float c[2][4];
#pragma unroll
        for (int i = 0; i < 2; i++)
#pragma unroll
            for (int j = 0; j < 4; j++) c[i][j] = 0.f;

        const uint32_t* Kb = KV + p*KVBUF;
#pragma unroll
        for (int ks = 0; ks < 8; ks++) {
            int k0 = ks * 8;
            uint32_t a0 = Qs[(m0+qr)*QST + k0 + qc];
            uint32_t a1 = Qs[(m0+qr+8)*QST + k0 + qc];
            uint32_t a2 = Qs[(m0+qr)*QST + k0 + 4 + qc];
            uint32_t a3 = Qs[(m0+qr+8)*QST + k0 + 4 + qc];
#pragma unroll
            for (int nt = 0; nt < 2; nt++) {
                int n = wn*16 + nt*8 + qr;
                uint32_t b0 = Kb[n*KST + k0 + qc];
                uint32_t b1 = Kb[n*KST + k0 + 4 + qc];
                mma_tf32(c[nt][0], c[nt][1], c[nt][2], c[nt][3], a0, a1, a2, a3, b0, b1);
            }
        }
#pragma unroll
        for (int nt = 0; nt < 2; nt++) {
            int col = kt*128 + wn*16 + nt*8 + 2*qc;
            int r0 = m0 + qr, r1 = r0 + 8;
            *(float2*)(S + r0*SPAD + col) = make_float2(c[nt][0]*scale + cl0[nt].x,
                                                        c[nt][1]*scale + cl0[nt].y);
            *(float2*)(S + r1*SPAD + col) = make_float2(c[nt][2]*scale + cl1[nt].x,
                                                        c[nt][3]*scale + cl1[nt].y);
        }
        if (kt < 7) STS_K(p ^ 1);
        __syncthreads();
    }

    // ---- row softmax (2 passes): store unnormalized exp + inv per row ----
#pragma unroll
    for (int r = 0; r < 2; r++) {
        int row = wid*2 + r;
        float mx = -1e30f;
        for (int i = lane; i < NKV; i += 32) mx = fmaxf(mx, S[row*SPAD + i]);
#pragma unroll
        for (int o = 16; o; o >>= 1) mx = fmaxf(mx, __shfl_xor_sync(0xffffffffu, mx, o));
        float ssum = 0.0f;
        for (int i = lane; i < NKV; i += 32) {
            float e = __expf(S[row*SPAD + i] - mx);
            S[row*SPAD + i] = e;
            ssum += e;
        }
#pragma unroll
        for (int o = 16; o; o >>= 1) ssum += __shfl_xor_sync(0xffffffffu, ssum, o);
        if (lane == 0) invs[row] = 1.0f / ssum;
    }
    __syncthreads();

    // ---- head-mean accumulation (normalized on the fly) ----
    for (int i = t; i < QTILE*NKV/4; i += 512) {
        int r = i >> 8, k4 = i & 255;
        float f = invs[r] * 0.0625f;
        float4 w = *(float4*)(S + r*SPAD + k4*4);
        w.x *= f; w.y *= f; w.z *= f; w.w *= f;
        red_add_v4(AM + ((size_t)(b*NQ + q0 + r))*NKV + k4*4, w);
    }

    // ---- O = S @ V, double-buffered; a-frags scaled by inv ----
    float o[4] = {0.f, 0.f, 0.f, 0.f};
    int n0 = wn * 8;
    float inv0 = invs[m0 + qr], inv1 = invs[m0 + qr + 8];

    LDG_V(0);
    __syncthreads();          // all reds/softmax reads of S done is not needed; KV buf0 free
    STS_V(0);
    __syncthreads();

    for (int kt = 0; kt < NKV/128; kt++) {
        int p = kt & 1;
        if (kt < 7) LDG_V(kt + 1);
        const uint32_t* Vb = KV + p*KVBUF;
#pragma unroll
        for (int ks = 0; ks < 16; ks++) {
            int k0 = kt*128 + ks*8;
            int kl = ks*8;
            uint32_t a0 = f2tf32(S[(m0+qr)*SPAD + k0 + qc] * inv0);
            uint32_t a1 = f2tf32(S[(m0+qr+8)*SPAD + k0 + qc] * inv1);
            uint32_t a2 = f2tf32(S[(m0+qr)*SPAD + k0 + 4 + qc] * inv0);
            uint32_t a3 = f2tf32(S[(m0+qr+8)*SPAD + k0 + 4 + qc] * inv1);
            uint32_t b0 = Vb[(kl + qc)*VST + n0 + qr];
            uint32_t b1 = Vb[(kl + 4 + qc)*VST + n0 + qr];
            mma_tf32(o[0], o[1], o[2], o[3], a0, a1, a2, a3, b0, b1);
        }
        if (kt < 7) STS_V(p ^ 1);
        __syncthreads();
    }
    // write AO
    {
        int col = n0 + 2*qc;
        int r0 = m0 + qr, r1 = r0 + 8;
        *(float2*)(AO + ((size_t)(b*NQ + q0 + r0))*DIM + h*HD + col) = make_float2(o[0], o[1]);
        *(float2*)(AO + ((size_t)(b*NQ + q0 + r1))*DIM + h*HD + col) = make_float2(o[2], o[3]);
    }
}

// ---------------------------------------------------------------------------
extern "C" void kernel_launch(void* const* d_in, const int* in_sizes, int n_in,
                              void* d_out, int out_size) {
    const float* query = (const float*)d_in[0];
    const float* kv    = (const float*)d_in[1];
    const float* cl    = (const float*)d_in[2];
    const float* Wq    = (const float*)d_in[3];
    const float* bq    = (const float*)d_in[4];
    const float* Wk    = (const float*)d_in[5];
    const float* bk    = (const float*)d_in[6];
    const float* Wv    = (const float*)d_in[7];
    const float* bv    = (const float*)d_in[8];
    const float* Wo    = (const float*)d_in[9];
    const float* bo    = (const float*)d_in[10];

    float* out_uq = (float*)d_out;
    float* out_am = out_uq + (size_t)BB*NQ*NKV;

    float *gQ, *gK, *gV, *gAO;
    cudaGetSymbolAddress((void**)&gQ,  g_Q);
    cudaGetSymbolAddress((void**)&gK,  g_K);
    cudaGetSymbolAddress((void**)&gV,  g_V);
    cudaGetSymbolAddress((void**)&gAO, g_AO);

    const int smem_attn = (QTILE*SPAD + QTILE*QST + 2*KVBUF + 32) * (int)sizeof(float);
    cudaFuncSetAttribute(attn_kernel, cudaFuncAttributeMaxDynamicSharedMemorySize, smem_attn);
    cudaFuncSetAttribute(gemm_mma, cudaFuncAttributeMaxDynamicSharedMemorySize, SMEM_G);

    zero_kernel<<<2048, 256>>>((float4*)out_am, BB*NQ*NKV/4);

    dim3 gg(DIM/128, M_TOT/128);   // (8, 64)
    gemm_mma<<<gg, 256, SMEM_G>>>(query, Wq, bq, gQ);
    gemm_mma<<<gg, 256, SMEM_G>>>(kv,    Wk, bk, gK);
    gemm_mma<<<gg, 256, SMEM_G>>>(kv,    Wv, bv, gV);

    attn_kernel<<<BB*NH*(NQ/QTILE), 512, smem_attn>>>(gQ, gK, gV, cl, gAO, out_am);

    gemm_mma<<<gg, 256, SMEM_G>>>(gAO, Wo, bo, out_uq);
}

// round 7
// speedup vs baseline: 6.5736x; 1.0907x over previous
#include <cuda_runtime.h>
#include <cstdint>

#define BB 8
#define NQ 1024
#define NKV 1024
#define DIM 1024
#define NH 16
#define HD 64
#define M_TOT (BB*NQ)   // 8192
#define QTILE 32
#define SPAD 1028       // S row stride (floats): %32==4 -> conflict-free frag reads
#define QST 68          // Q smem stride (tf32)
#define KST 68          // K tile stride (tf32)
#define VST 72          // V tile stride (tf32)
#define KVBUF (128*VST) // one K/V buffer (tf32 words)

// Scratch (allocation-free rule: __device__ globals)
__device__ float g_Q [M_TOT*DIM];
__device__ float g_K [M_TOT*DIM];
__device__ float g_V [M_TOT*DIM];
__device__ float g_AO[M_TOT*DIM];

// ---------------------------------------------------------------------------
__device__ __forceinline__ uint32_t f2tf32(float x) {
    uint32_t u;
    asm("cvt.rna.tf32.f32 %0, %1;" : "=r"(u) : "f"(x));
    return u;
}
__device__ __forceinline__ void mma_tf32(float& c0, float& c1, float& c2, float& c3,
                                         uint32_t a0, uint32_t a1, uint32_t a2, uint32_t a3,
                                         uint32_t b0, uint32_t b1) {
    asm volatile(
        "mma.sync.aligned.m16n8k8.row.col.f32.tf32.tf32.f32 "
        "{%0,%1,%2,%3}, {%4,%5,%6,%7}, {%8,%9}, {%0,%1,%2,%3};"
        : "+f"(c0), "+f"(c1), "+f"(c2), "+f"(c3)
        : "r"(a0), "r"(a1), "r"(a2), "r"(a3), "r"(b0), "r"(b1));
}
__device__ __forceinline__ void red_add_v4(float* p, float4 v) {
    asm volatile("red.global.add.v4.f32 [%0], {%1,%2,%3,%4};"
                 :: "l"(p), "f"(v.x), "f"(v.y), "f"(v.z), "f"(v.w) : "memory");
}

// ---------------------------------------------------------------------------
// GEMM body: Y[128x128 tile at (bx,by)] = X @ W^T + bias. 256 threads.
// ---------------------------------------------------------------------------
#define GST 36
#define GBUF (128*GST)
#define SMEM_G (512 + 4*GBUF*4)

__device__ __forceinline__
void gemm_body(const float* __restrict__ X, const float* __restrict__ W,
               const float* __restrict__ bias, float* __restrict__ Y,
               int bx, int by) {
    extern __shared__ float sm[];
    float* bias_s = sm;
    uint32_t* As = (uint32_t*)(sm + 128);
    uint32_t* Bs = As + 2*GBUF;

    int t = threadIdx.x, lane = t & 31, wid = t >> 5;
    int bm = by * 128, bn = bx * 128;
    int wm = wid & 3, wn = wid >> 2;

    if (t < 128) bias_s[t] = bias[bn + t];

    int r0g = t >> 3;
    int c4 = t & 7;

    float4 ra[4], rb[4];
    auto LDG = [&](int kt) {
#pragma unroll
        for (int i = 0; i < 4; i++) {
            int r = r0g + 32*i;
            ra[i] = *(const float4*)(X + (size_t)(bm + r)*DIM + kt*32 + c4*4);
            rb[i] = *(const float4*)(W + (size_t)(bn + r)*DIM + kt*32 + c4*4);
        }
    };
    auto STS = [&](int p) {
#pragma unroll
        for (int i = 0; i < 4; i++) {
            int r = r0g + 32*i;
            uint32_t* pa = As + p*GBUF + r*GST + c4*4;
            uint32_t* pb = Bs + p*GBUF + r*GST + c4*4;
            pa[0] = f2tf32(ra[i].x); pa[1] = f2tf32(ra[i].y);
            pa[2] = f2tf32(ra[i].z); pa[3] = f2tf32(ra[i].w);
            pb[0] = f2tf32(rb[i].x); pb[1] = f2tf32(rb[i].y);
            pb[2] = f2tf32(rb[i].z); pb[3] = f2tf32(rb[i].w);
        }
    };

    float c[2][8][4];
#pragma unroll
    for (int i = 0; i < 2; i++)
#pragma unroll
        for (int j = 0; j < 8; j++)
#pragma unroll
            for (int k = 0; k < 4; k++) c[i][j][k] = 0.f;

    LDG(0); STS(0);
    __syncthreads();

    int qr = lane >> 2, qc = lane & 3;
    for (int kt = 0; kt < DIM/32; kt++) {
        int p = kt & 1;
        if (kt < DIM/32 - 1) LDG(kt + 1);
        const uint32_t* Ab = As + p*GBUF;
        const uint32_t* Bb = Bs + p*GBUF;
#pragma unroll
        for (int s = 0; s < 4; s++) {
            int k0 = s*8;
            uint32_t af[2][4], bf[8][2];
#pragma unroll
            for (int tm = 0; tm < 2; tm++) {
                int row = wm*32 + tm*16 + qr;
                af[tm][0] = Ab[row*GST + k0 + qc];
                af[tm][1] = Ab[(row+8)*GST + k0 + qc];
                af[tm][2] = Ab[row*GST + k0 + 4 + qc];
                af[tm][3] = Ab[(row+8)*GST + k0 + 4 + qc];
            }
#pragma unroll
            for (int tn = 0; tn < 8; tn++) {
                int n = wn*64 + tn*8 + qr;
                bf[tn][0] = Bb[n*GST + k0 + qc];
                bf[tn][1] = Bb[n*GST + k0 + 4 + qc];
            }
#pragma unroll
            for (int tm = 0; tm < 2; tm++)
#pragma unroll
                for (int tn = 0; tn < 8; tn++)
                    mma_tf32(c[tm][tn][0], c[tm][tn][1], c[tm][tn][2], c[tm][tn][3],
                             af[tm][0], af[tm][1], af[tm][2], af[tm][3],
                             bf[tn][0], bf[tn][1]);
        }
        if (kt < DIM/32 - 1) STS(p ^ 1);
        __syncthreads();
    }

#pragma unroll
    for (int tm = 0; tm < 2; tm++) {
        int row = bm + wm*32 + tm*16 + qr;
#pragma unroll
        for (int tn = 0; tn < 8; tn++) {
            int col = wn*64 + tn*8 + qc*2;
            float2 v0 = { c[tm][tn][0] + bias_s[col], c[tm][tn][1] + bias_s[col+1] };
            float2 v1 = { c[tm][tn][2] + bias_s[col], c[tm][tn][3] + bias_s[col+1] };
            *(float2*)(Y + (size_t)row*DIM + bn + col)     = v0;
            *(float2*)(Y + (size_t)(row+8)*DIM + bn + col) = v1;
        }
    }
}

// ---------------------------------------------------------------------------
// Fused QKV projections + AM zeroing: 1792 blocks.
//   [0,512)    Q = query @ Wq^T + bq
//   [512,1024) K = kv @ Wk^T + bk
//   [1024,1536)V = kv @ Wv^T + bv
//   [1536,1792) zero attn_matrix (grid-stride)
// ---------------------------------------------------------------------------
__global__ __launch_bounds__(256, 2)
void qkv_zero_kernel(const float* __restrict__ query, const float* __restrict__ kv,
                     const float* __restrict__ Wq, const float* __restrict__ bq,
                     const float* __restrict__ Wk, const float* __restrict__ bk,
                     const float* __restrict__ Wv, const float* __restrict__ bv,
                     float* __restrict__ gQ, float* __restrict__ gK, float* __restrict__ gV,
                     float4* __restrict__ am4, int n4) {
    int g = blockIdx.x;
    if (g >= 1536) {
        float4 z = {0.f, 0.f, 0.f, 0.f};
        for (int i = (g - 1536)*256 + threadIdx.x; i < n4; i += 256*256) am4[i] = z;
        return;
    }
    int which = g >> 9;
    int bx = g & 7, by = (g & 511) >> 3;
    const float* X    = (which == 0) ? query : kv;
    const float* W    = (which == 0) ? Wq : (which == 1 ? Wk : Wv);
    const float* bias = (which == 0) ? bq : (which == 1 ? bk : bv);
    float*       Y    = (which == 0) ? gQ : (which == 1 ? gK : gV);
    gemm_body(X, W, bias, Y, bx, by);
}

// Final output projection (single GEMM)
__global__ __launch_bounds__(256, 2)
void gemm_mma(const float* __restrict__ X, const float* __restrict__ W,
              const float* __restrict__ bias, float* __restrict__ Y) {
    gemm_body(X, W, bias, Y, blockIdx.x, blockIdx.y);
}

// ---------------------------------------------------------------------------
// Attention, 512 threads = 16 warps, double-buffered K/V, fused normalization,
// CL prefetch pipelined one chunk ahead, V load overlapped with AM reds.
// ---------------------------------------------------------------------------
__global__ __launch_bounds__(512)
void attn_kernel(const float* __restrict__ Q, const float* __restrict__ K,
                 const float* __restrict__ V, const float* __restrict__ CL,
                 float* __restrict__ AO, float* __restrict__ AM) {
    extern __shared__ float sm[];
    float* S = sm;                               // 32*SPAD fp32
    uint32_t* Qs = (uint32_t*)(S + QTILE*SPAD);  // 32*QST tf32
    uint32_t* KV = Qs + QTILE*QST;               // 2 * KVBUF tf32
    float* invs = (float*)(KV + 2*KVBUF);        // 32 floats

    int blk = blockIdx.x;
    int qt = blk & 31;
    int h  = (blk >> 5) & 15;
    int b  = blk >> 9;
    int q0 = qt * QTILE;
    int t  = threadIdx.x;
    int lane = t & 31, wid = t >> 5;
    int qr = lane >> 2, qc = lane & 3;
    int wm = wid & 1, wn = wid >> 1;
    int m0 = wm * 16;
    const float scale = 0.125f;

    int ldr = t >> 4;
    int ldd = t & 15;

    const float* Kbase = K + ((size_t)(b*NKV))*DIM + h*HD;
    const float* Vbase = V + ((size_t)(b*NKV))*DIM + h*HD;

    float4 rk[4];
    auto LDG_K = [&](int kt) {
#pragma unroll
        for (int i = 0; i < 4; i++) {
            int ki = ldr + i*32;
            rk[i] = *(const float4*)(Kbase + (size_t)(kt*128 + ki)*DIM + ldd*4);
        }
    };
    auto STS_K = [&](int p) {
#pragma unroll
        for (int i = 0; i < 4; i++) {
            int ki = ldr + i*32;
            uint32_t* q = KV + p*KVBUF + ki*KST + ldd*4;
            q[0] = f2tf32(rk[i].x); q[1] = f2tf32(rk[i].y);
            q[2] = f2tf32(rk[i].z); q[3] = f2tf32(rk[i].w);
        }
    };
    auto LDG_V = [&](int kt) {
#pragma unroll
        for (int i = 0; i < 4; i++) {
            int ki = ldr + i*32;
            rk[i] = *(const float4*)(Vbase + (size_t)(kt*128 + ki)*DIM + ldd*4);
        }
    };
    auto STS_V = [&](int p) {
#pragma unroll
        for (int i = 0; i < 4; i++) {
            int ki = ldr + i*32;
            uint32_t* q = KV + p*KVBUF + ki*VST + ldd*4;
            q[0] = f2tf32(rk[i].x); q[1] = f2tf32(rk[i].y);
            q[2] = f2tf32(rk[i].z); q[3] = f2tf32(rk[i].w);
        }
    };

    // load Q tile [32,64] -> tf32 smem
    {
        int qi = t >> 4, d4 = t & 15;
        float4 v = *(const float4*)(Q + ((size_t)(b*NQ + q0 + qi))*DIM + h*HD + d4*4);
        uint32_t* p = Qs + qi*QST + d4*4;
        p[0] = f2tf32(v.x); p[1] = f2tf32(v.y); p[2] = f2tf32(v.z); p[3] = f2tf32(v.w);
    }
    LDG_K(0); STS_K(0);

    // CL prefetch pipeline
    const float* CLr0 = CL + ((size_t)(b*NQ + q0 + m0 + qr))*NKV;
    const float* CLr1 = CLr0 + (size_t)8*NKV;
    float2 cl0[2], cl1[2], ncl0[2], ncl1[2];
#pragma unroll
    for (int nt = 0; nt < 2; nt++) {
        int col = wn*16 + nt*8 + 2*qc;
        cl0[nt] = *(const float2*)(CLr0 + col);
        cl1[nt] = *(const float2*)(CLr1 + col);
    }
    __syncthreads();

    // ---- QK^T, double-buffered ----
    for (int kt = 0; kt < NKV/128; kt++) {
        int p = kt & 1;
        if (kt < 7) {
            LDG_K(kt + 1);
#pragma unroll
            for (int nt = 0; nt < 2; nt++) {
                int col = (kt+1)*128 + wn*16 + nt*8 + 2*qc;
                ncl0[nt] = *(const float2*)(CLr0 + col);
                ncl1[nt] = *(const float2*)(CLr1 + col);
            }
        }

        float c[2][4];
#pragma unroll
        for (int i = 0; i < 2; i++)
#pragma unroll
            for (int j = 0; j < 4; j++) c[i][j] = 0.f;

        const uint32_t* Kb = KV + p*KVBUF;
#pragma unroll
        for (int ks = 0; ks < 8; ks++) {
            int k0 = ks * 8;
            uint32_t a0 = Qs[(m0+qr)*QST + k0 + qc];
            uint32_t a1 = Qs[(m0+qr+8)*QST + k0 + qc];
            uint32_t a2 = Qs[(m0+qr)*QST + k0 + 4 + qc];
            uint32_t a3 = Qs[(m0+qr+8)*QST + k0 + 4 + qc];
#pragma unroll
            for (int nt = 0; nt < 2; nt++) {
                int n = wn*16 + nt*8 + qr;
                uint32_t b0 = Kb[n*KST + k0 + qc];
                uint32_t b1 = Kb[n*KST + k0 + 4 + qc];
                mma_tf32(c[nt][0], c[nt][1], c[nt][2], c[nt][3], a0, a1, a2, a3, b0, b1);
            }
        }
#pragma unroll
        for (int nt = 0; nt < 2; nt++) {
            int col = kt*128 + wn*16 + nt*8 + 2*qc;
            int r0 = m0 + qr, r1 = r0 + 8;
            *(float2*)(S + r0*SPAD + col) = make_float2(c[nt][0]*scale + cl0[nt].x,
                                                        c[nt][1]*scale + cl0[nt].y);
            *(float2*)(S + r1*SPAD + col) = make_float2(c[nt][2]*scale + cl1[nt].x,
                                                        c[nt][3]*scale + cl1[nt].y);
        }
        if (kt < 7) {
            STS_K(p ^ 1);
#pragma unroll
            for (int nt = 0; nt < 2; nt++) { cl0[nt] = ncl0[nt]; cl1[nt] = ncl1[nt]; }
        }
        __syncthreads();
    }

    // ---- row softmax: unnormalized exp + inv per row ----
#pragma unroll
    for (int r = 0; r < 2; r++) {
        int row = wid*2 + r;
        float mx = -1e30f;
        for (int i = lane; i < NKV; i += 32) mx = fmaxf(mx, S[row*SPAD + i]);
#pragma unroll
        for (int o = 16; o; o >>= 1) mx = fmaxf(mx, __shfl_xor_sync(0xffffffffu, mx, o));
        float ssum = 0.0f;
        for (int i = lane; i < NKV; i += 32) {
            float e = __expf(S[row*SPAD + i] - mx);
            S[row*SPAD + i] = e;
            ssum += e;
        }
#pragma unroll
        for (int o = 16; o; o >>= 1) ssum += __shfl_xor_sync(0xffffffffu, ssum, o);
        if (lane == 0) invs[row] = 1.0f / ssum;
    }
    __syncthreads();

    // start V chunk-0 load; its latency hides behind the AM red storm
    LDG_V(0);

    // ---- head-mean accumulation (normalized on the fly) ----
    for (int i = t; i < QTILE*NKV/4; i += 512) {
        int r = i >> 8, k4 = i & 255;
        float f = invs[r] * 0.0625f;
        float4 w = *(float4*)(S + r*SPAD + k4*4);
        w.x *= f; w.y *= f; w.z *= f; w.w *= f;
        red_add_v4(AM + ((size_t)(b*NQ + q0 + r))*NKV + k4*4, w);
    }

    // KV buffers free since pre-softmax sync; stage V chunk 0
    STS_V(0);
    __syncthreads();

    // ---- O = S @ V, double-buffered; a-frags scaled by inv ----
    float o[4] = {0.f, 0.f, 0.f, 0.f};
    int n0 = wn * 8;
    float inv0 = invs[m0 + qr], inv1 = invs[m0 + qr + 8];

    for (int kt = 0; kt < NKV/128; kt++) {
        int p = kt & 1;
        if (kt < 7) LDG_V(kt + 1);
        const uint32_t* Vb = KV + p*KVBUF;
#pragma unroll
        for (int ks = 0; ks < 16; ks++) {
            int k0 = kt*128 + ks*8;
            int kl = ks*8;
            uint32_t a0 = f2tf32(S[(m0+qr)*SPAD + k0 + qc] * inv0);
            uint32_t a1 = f2tf32(S[(m0+qr+8)*SPAD + k0 + qc] * inv1);
            uint32_t a2 = f2tf32(S[(m0+qr)*SPAD + k0 + 4 + qc] * inv0);
            uint32_t a3 = f2tf32(S[(m0+qr+8)*SPAD + k0 + 4 + qc] * inv1);
            uint32_t b0 = Vb[(kl + qc)*VST + n0 + qr];
            uint32_t b1 = Vb[(kl + 4 + qc)*VST + n0 + qr];
            mma_tf32(o[0], o[1], o[2], o[3], a0, a1, a2, a3, b0, b1);
        }
        if (kt < 7) STS_V(p ^ 1);
        __syncthreads();
    }
    // write AO
    {
        int col = n0 + 2*qc;
        int r0 = m0 + qr, r1 = r0 + 8;
        *(float2*)(AO + ((size_t)(b*NQ + q0 + r0))*DIM + h*HD + col) = make_float2(o[0], o[1]);
        *(float2*)(AO + ((size_t)(b*NQ + q0 + r1))*DIM + h*HD + col) = make_float2(o[2], o[3]);
    }
}

// ---------------------------------------------------------------------------
extern "C" void kernel_launch(void* const* d_in, const int* in_sizes, int n_in,
                              void* d_out, int out_size) {
    const float* query = (const float*)d_in[0];
    const float* kv    = (const float*)d_in[1];
    const float* cl    = (const float*)d_in[2];
    const float* Wq    = (const float*)d_in[3];
    const float* bq    = (const float*)d_in[4];
    const float* Wk    = (const float*)d_in[5];
    const float* bk    = (const float*)d_in[6];
    const float* Wv    = (const float*)d_in[7];
    const float* bv    = (const float*)d_in[8];
    const float* Wo    = (const float*)d_in[9];
    const float* bo    = (const float*)d_in[10];

    float* out_uq = (float*)d_out;
    float* out_am = out_uq + (size_t)BB*NQ*NKV;

    float *gQ, *gK, *gV, *gAO;
    cudaGetSymbolAddress((void**)&gQ,  g_Q);
    cudaGetSymbolAddress((void**)&gK,  g_K);
    cudaGetSymbolAddress((void**)&gV,  g_V);
    cudaGetSymbolAddress((void**)&gAO, g_AO);

    const int smem_attn = (QTILE*SPAD + QTILE*QST + 2*KVBUF + 32) * (int)sizeof(float);
    cudaFuncSetAttribute(attn_kernel, cudaFuncAttributeMaxDynamicSharedMemorySize, smem_attn);
    cudaFuncSetAttribute(gemm_mma, cudaFuncAttributeMaxDynamicSharedMemorySize, SMEM_G);
    cudaFuncSetAttribute(qkv_zero_kernel, cudaFuncAttributeMaxDynamicSharedMemorySize, SMEM_G);

    // fused QKV projections + attn_matrix zeroing
    qkv_zero_kernel<<<1792, 256, SMEM_G>>>(query, kv, Wq, bq, Wk, bk, Wv, bv,
                                           gQ, gK, gV,
                                           (float4*)out_am, BB*NQ*NKV/4);

    attn_kernel<<<BB*NH*(NQ/QTILE), 512, smem_attn>>>(gQ, gK, gV, cl, gAO, out_am);

    dim3 gg(DIM/128, M_TOT/128);   // (8, 64)
    gemm_mma<<<gg, 256, SMEM_G>>>(gAO, Wo, bo, out_uq);
}

// round 8
// speedup vs baseline: 6.9847x; 1.0625x over previous
#include <cuda_runtime.h>
#include <cstdint>

#define BB 8
#define NQ 1024
#define NKV 1024
#define DIM 1024
#define NH 16
#define HD 64
#define M_TOT (BB*NQ)   // 8192

// attention tiling
#define AQT 64          // q rows per block
#define AQST 68         // Q smem stride (tf32 words)
#define AKST 68         // K/V smem stride (f32 words)
#define AEST 68         // e-stage stride
#define AKW (128*AKST)  // one K/V buffer (words)

// Scratch (allocation-free rule: __device__ globals)
__device__ float g_Q [M_TOT*DIM];
__device__ float g_K [M_TOT*DIM];
__device__ float g_V [M_TOT*DIM];
__device__ float g_AO[M_TOT*DIM];

// ---------------------------------------------------------------------------
__device__ __forceinline__ uint32_t smem_u32(const void* p) {
    uint32_t a;
    asm("{ .reg .u64 t; cvta.to.shared.u64 t, %1; cvt.u32.u64 %0, t; }" : "=r"(a) : "l"(p));
    return a;
}
__device__ __forceinline__ uint32_t f2tf32(float x) {
    uint32_t u;
    asm("cvt.rna.tf32.f32 %0, %1;" : "=r"(u) : "f"(x));
    return u;
}
__device__ __forceinline__ void mma_tf32(float& c0, float& c1, float& c2, float& c3,
                                         uint32_t a0, uint32_t a1, uint32_t a2, uint32_t a3,
                                         uint32_t b0, uint32_t b1) {
    asm volatile(
        "mma.sync.aligned.m16n8k8.row.col.f32.tf32.tf32.f32 "
        "{%0,%1,%2,%3}, {%4,%5,%6,%7}, {%8,%9}, {%0,%1,%2,%3};"
        : "+f"(c0), "+f"(c1), "+f"(c2), "+f"(c3)
        : "r"(a0), "r"(a1), "r"(a2), "r"(a3), "r"(b0), "r"(b1));
}
__device__ __forceinline__ void red_add_v2(float* p, float x, float y) {
    asm volatile("red.global.add.v2.f32 [%0], {%1,%2};"
                 :: "l"(p), "f"(x), "f"(y) : "memory");
}
__device__ __forceinline__ void cpasync16(uint32_t dst, const void* src) {
    asm volatile("cp.async.ca.shared.global [%0], [%1], 16;" :: "r"(dst), "l"(src) : "memory");
}
#define CP_COMMIT() asm volatile("cp.async.commit_group;" ::: "memory")
#define CP_WAIT(n)  asm volatile("cp.async.wait_group %0;" :: "n"(n) : "memory")

// ---------------------------------------------------------------------------
// GEMM body (unchanged, proven): Y[128x128 tile] = X @ W^T + bias. 256 thr.
// ---------------------------------------------------------------------------
#define GST 36
#define GBUF (128*GST)
#define SMEM_G (512 + 4*GBUF*4)

__device__ __forceinline__
void gemm_body(const float* __restrict__ X, const float* __restrict__ W,
               const float* __restrict__ bias, float* __restrict__ Y,
               int bx, int by) {
    extern __shared__ float sm[];
    float* bias_s = sm;
    uint32_t* As = (uint32_t*)(sm + 128);
    uint32_t* Bs = As + 2*GBUF;

    int t = threadIdx.x, lane = t & 31, wid = t >> 5;
    int bm = by * 128, bn = bx * 128;
    int wm = wid & 3, wn = wid >> 2;

    if (t < 128) bias_s[t] = bias[bn + t];

    int r0g = t >> 3;
    int c4 = t & 7;

    float4 ra[4], rb[4];
    auto LDG = [&](int kt) {
#pragma unroll
        for (int i = 0; i < 4; i++) {
            int r = r0g + 32*i;
            ra[i] = *(const float4*)(X + (size_t)(bm + r)*DIM + kt*32 + c4*4);
            rb[i] = *(const float4*)(W + (size_t)(bn + r)*DIM + kt*32 + c4*4);
        }
    };
    auto STS = [&](int p) {
#pragma unroll
        for (int i = 0; i < 4; i++) {
            int r = r0g + 32*i;
            uint32_t* pa = As + p*GBUF + r*GST + c4*4;
            uint32_t* pb = Bs + p*GBUF + r*GST + c4*4;
            pa[0] = f2tf32(ra[i].x); pa[1] = f2tf32(ra[i].y);
            pa[2] = f2tf32(ra[i].z); pa[3] = f2tf32(ra[i].w);
            pb[0] = f2tf32(rb[i].x); pb[1] = f2tf32(rb[i].y);
            pb[2] = f2tf32(rb[i].z); pb[3] = f2tf32(rb[i].w);
        }
    };

    float c[2][8][4];
#pragma unroll
    for (int i = 0; i < 2; i++)
#pragma unroll
        for (int j = 0; j < 8; j++)
#pragma unroll
            for (int k = 0; k < 4; k++) c[i][j][k] = 0.f;

    LDG(0); STS(0);
    __syncthreads();

    int qr = lane >> 2, qc = lane & 3;
    for (int kt = 0; kt < DIM/32; kt++) {
        int p = kt & 1;
        if (kt < DIM/32 - 1) LDG(kt + 1);
        const uint32_t* Ab = As + p*GBUF;
        const uint32_t* Bb = Bs + p*GBUF;
#pragma unroll
        for (int s = 0; s < 4; s++) {
            int k0 = s*8;
            uint32_t af[2][4], bf[8][2];
#pragma unroll
            for (int tm = 0; tm < 2; tm++) {
                int row = wm*32 + tm*16 + qr;
                af[tm][0] = Ab[row*GST + k0 + qc];
                af[tm][1] = Ab[(row+8)*GST + k0 + qc];
                af[tm][2] = Ab[row*GST + k0 + 4 + qc];
                af[tm][3] = Ab[(row+8)*GST + k0 + 4 + qc];
            }
#pragma unroll
            for (int tn = 0; tn < 8; tn++) {
                int n = wn*64 + tn*8 + qr;
                bf[tn][0] = Bb[n*GST + k0 + qc];
                bf[tn][1] = Bb[n*GST + k0 + 4 + qc];
            }
#pragma unroll
            for (int tm = 0; tm < 2; tm++)
#pragma unroll
                for (int tn = 0; tn < 8; tn++)
                    mma_tf32(c[tm][tn][0], c[tm][tn][1], c[tm][tn][2], c[tm][tn][3],
                             af[tm][0], af[tm][1], af[tm][2], af[tm][3],
                             bf[tn][0], bf[tn][1]);
        }
        if (kt < DIM/32 - 1) STS(p ^ 1);
        __syncthreads();
    }

#pragma unroll
    for (int tm = 0; tm < 2; tm++) {
        int row = bm + wm*32 + tm*16 + qr;
#pragma unroll
        for (int tn = 0; tn < 8; tn++) {
            int col = wn*64 + tn*8 + qc*2;
            float2 v0 = { c[tm][tn][0] + bias_s[col], c[tm][tn][1] + bias_s[col+1] };
            float2 v1 = { c[tm][tn][2] + bias_s[col], c[tm][tn][3] + bias_s[col+1] };
            *(float2*)(Y + (size_t)row*DIM + bn + col)     = v0;
            *(float2*)(Y + (size_t)(row+8)*DIM + bn + col) = v1;
        }
    }
}

// Fused QKV projections + AM zeroing
__global__ __launch_bounds__(256, 2)
void qkv_zero_kernel(const float* __restrict__ query, const float* __restrict__ kv,
                     const float* __restrict__ Wq, const float* __restrict__ bq,
                     const float* __restrict__ Wk, const float* __restrict__ bk,
                     const float* __restrict__ Wv, const float* __restrict__ bv,
                     float* __restrict__ gQ, float* __restrict__ gK, float* __restrict__ gV,
                     float4* __restrict__ am4, int n4) {
    int g = blockIdx.x;
    if (g >= 1536) {
        float4 z = {0.f, 0.f, 0.f, 0.f};
        for (int i = (g - 1536)*256 + threadIdx.x; i < n4; i += 256*256) am4[i] = z;
        return;
    }
    int which = g >> 9;
    int bx = g & 7, by = (g & 511) >> 3;
    const float* X    = (which == 0) ? query : kv;
    const float* W    = (which == 0) ? Wq : (which == 1 ? Wk : Wv);
    const float* bias = (which == 0) ? bq : (which == 1 ? bk : bv);
    float*       Y    = (which == 0) ? gQ : (which == 1 ? gK : gV);
    gemm_body(X, W, bias, Y, bx, by);
}

__global__ __launch_bounds__(256, 2)
void gemm_mma(const float* __restrict__ X, const float* __restrict__ W,
              const float* __restrict__ bias, float* __restrict__ Y) {
    gemm_body(X, W, bias, Y, blockIdx.x, blockIdx.y);
}

// ---------------------------------------------------------------------------
// Flash-style attention: QTILE=64, 256 threads (8 warps), 2-pass online
// softmax, cp.async K/V staging (raw f32 -> tf32-truncating MMA), e staged
// per half-chunk in smem, AM head-mean via red.global.v2.
// smem (floats): Qs[64*68] | KA[128*68] | KB[128*68] | Es[64*68]
//                | Mw[128] Sw[128] Mf[64] If[64]
// ---------------------------------------------------------------------------
#define ASM_WORDS (AQT*AQST + 2*AKW + AQT*AEST + 384)

__global__ __launch_bounds__(256, 2)
void attn_kernel(const float* __restrict__ Q, const float* __restrict__ K,
                 const float* __restrict__ V, const float* __restrict__ CL,
                 float* __restrict__ AO, float* __restrict__ AM) {
    extern __shared__ float sm[];
    float* Qsf = sm;                 // 64*AQST (tf32 bits)
    float* KA  = Qsf + AQT*AQST;     // 128*AKST
    float* KB  = KA + AKW;           // 128*AKST
    float* Es  = KB + AKW;           // 64*AEST
    float* Mw  = Es + AQT*AEST;      // [2][64]
    float* Sw  = Mw + 128;           // [2][64]
    float* Mf  = Sw + 128;           // [64]
    float* If_ = Mf + 64;            // [64]

    const uint32_t* Qs = (const uint32_t*)Qsf;
    uint32_t kaBase = smem_u32(KA), kbBase = smem_u32(KB);

    int blk = blockIdx.x;
    int qt = blk & 15;
    int h  = (blk >> 4) & 15;
    int b  = blk >> 8;
    int q0 = qt * AQT;
    int t  = threadIdx.x;
    int lane = t & 31, wid = t >> 5;
    int qr = lane >> 2, qc = lane & 3;
    int wm = wid & 3, wn = wid >> 2;   // pass1/QK: m-tile (16), k-col half (64)
    int m0 = wm * 16;
    const float scale = 0.125f;

    int ldr = t >> 4;                  // 0..15
    int ldd = t & 15;                  // 0..15 (float4 within 64-f row)

    const float* Kbase = K + ((size_t)(b*NKV))*DIM + h*HD;
    const float* Vbase = V + ((size_t)(b*NKV))*DIM + h*HD;

    auto CPA = [&](const float* gsrc, int kt, uint32_t sbase) {
#pragma unroll
        for (int i = 0; i < 8; i++) {
            int r = ldr + i*16;
            cpasync16(sbase + (uint32_t)(r*AKST + ldd*4)*4u,
                      gsrc + (size_t)(kt*128 + r)*DIM + ldd*4);
        }
        CP_COMMIT();
    };

    // Q tile -> tf32 smem
#pragma unroll
    for (int i = 0; i < 4; i++) {
        int f = t + i*256;
        int qi = f >> 4, d4 = f & 15;
        float4 v = *(const float4*)(Q + ((size_t)(b*NQ + q0 + qi))*DIM + h*HD + d4*4);
        uint32_t* p = (uint32_t*)Qsf + qi*AQST + d4*4;
        p[0] = f2tf32(v.x); p[1] = f2tf32(v.y); p[2] = f2tf32(v.z); p[3] = f2tf32(v.w);
    }
    CPA(Kbase, 0, kaBase);

    const float* CLr0 = CL + ((size_t)(b*NQ + q0 + m0 + qr))*NKV;
    const float* CLr1 = CLr0 + (size_t)8*NKV;

    float m_a = -1e30f, m_b = -1e30f, s_a = 0.f, s_b = 0.f;

    // ================= pass 1: scores + online (m, s) =================
    for (int kt = 0; kt < 8; kt++) {
        const uint32_t* Kb = (const uint32_t*)((kt & 1) ? KB : KA);
        if (kt < 7) { CPA(Kbase, kt + 1, (kt & 1) ? kaBase : kbBase); CP_WAIT(1); }
        else        { CP_WAIT(0); }
        __syncthreads();

        float c[8][4];
#pragma unroll
        for (int i = 0; i < 8; i++)
#pragma unroll
            for (int j = 0; j < 4; j++) c[i][j] = 0.f;
#pragma unroll
        for (int ks = 0; ks < 8; ks++) {
            int k0 = ks * 8;
            uint32_t a0 = Qs[(m0+qr)*AQST + k0 + qc];
            uint32_t a1 = Qs[(m0+qr+8)*AQST + k0 + qc];
            uint32_t a2 = Qs[(m0+qr)*AQST + k0 + 4 + qc];
            uint32_t a3 = Qs[(m0+qr+8)*AQST + k0 + 4 + qc];
#pragma unroll
            for (int nt = 0; nt < 8; nt++) {
                int n = wn*64 + nt*8 + qr;
                uint32_t b0 = Kb[n*AKST + k0 + qc];
                uint32_t b1 = Kb[n*AKST + k0 + 4 + qc];
                mma_tf32(c[nt][0], c[nt][1], c[nt][2], c[nt][3], a0, a1, a2, a3, b0, b1);
            }
        }
        float cma = -1e30f, cmb = -1e30f;
#pragma unroll
        for (int nt = 0; nt < 8; nt++) {
            int col = kt*128 + wn*64 + nt*8 + 2*qc;
            float2 cl0 = *(const float2*)(CLr0 + col);
            float2 cl1 = *(const float2*)(CLr1 + col);
            c[nt][0] = c[nt][0]*scale + cl0.x;
            c[nt][1] = c[nt][1]*scale + cl0.y;
            c[nt][2] = c[nt][2]*scale + cl1.x;
            c[nt][3] = c[nt][3]*scale + cl1.y;
            cma = fmaxf(cma, fmaxf(c[nt][0], c[nt][1]));
            cmb = fmaxf(cmb, fmaxf(c[nt][2], c[nt][3]));
        }
#pragma unroll
        for (int o = 1; o <= 2; o <<= 1) {
            cma = fmaxf(cma, __shfl_xor_sync(0xffffffffu, cma, o));
            cmb = fmaxf(cmb, __shfl_xor_sync(0xffffffffu, cmb, o));
        }
        float mna = fmaxf(m_a, cma), mnb = fmaxf(m_b, cmb);
        float sea = 0.f, seb = 0.f;
#pragma unroll
        for (int nt = 0; nt < 8; nt++) {
            sea += __expf(c[nt][0] - mna) + __expf(c[nt][1] - mna);
            seb += __expf(c[nt][2] - mnb) + __expf(c[nt][3] - mnb);
        }
#pragma unroll
        for (int o = 1; o <= 2; o <<= 1) {
            sea += __shfl_xor_sync(0xffffffffu, sea, o);
            seb += __shfl_xor_sync(0xffffffffu, seb, o);
        }
        s_a = s_a * __expf(m_a - mna) + sea;  m_a = mna;
        s_b = s_b * __expf(m_b - mnb) + seb;  m_b = mnb;
    }

    if (qc == 0) {
        Mw[wn*64 + m0 + qr]     = m_a;  Mw[wn*64 + m0 + qr + 8] = m_b;
        Sw[wn*64 + m0 + qr]     = s_a;  Sw[wn*64 + m0 + qr + 8] = s_b;
    }
    __syncthreads();                       // pass1 fully done (K bufs free)
    if (t < 64) {
        float mv0 = Mw[t], mv1 = Mw[64 + t];
        float m = fmaxf(mv0, mv1);
        float s = Sw[t]*__expf(mv0 - m) + Sw[64 + t]*__expf(mv1 - m);
        Mf[t] = m;  If_[t] = 1.0f / s;
    }
    CPA(Kbase, 0, kaBase);
    CPA(Vbase, 0, kbBase);
    CP_WAIT(1);                            // K(0) ready; V(0) pending
    __syncthreads();                       // Mf/If visible + K(0) visible

    float mf0 = Mf[m0 + qr], mf1 = Mf[m0 + qr + 8];
    float if0 = If_[m0 + qr], if1 = If_[m0 + qr + 8];

    // AV mapping: wm2 m-tile (4x16), wd d-half (2x32)
    int wm2 = wid & 3, wd = wid >> 2;
    int am0 = wm2 * 16;
    float o[4][4];
#pragma unroll
    for (int i = 0; i < 4; i++)
#pragma unroll
        for (int j = 0; j < 4; j++) o[i][j] = 0.f;

    // ================= pass 2: recompute + AM red + AV =================
    for (int kt = 0; kt < 8; kt++) {
        // ---- QK recompute from KA ----
        float c[8][4];
#pragma unroll
        for (int i = 0; i < 8; i++)
#pragma unroll
            for (int j = 0; j < 4; j++) c[i][j] = 0.f;
        const uint32_t* Kb = (const uint32_t*)KA;
#pragma unroll
        for (int ks = 0; ks < 8; ks++) {
            int k0 = ks * 8;
            uint32_t a0 = Qs[(m0+qr)*AQST + k0 + qc];
            uint32_t a1 = Qs[(m0+qr+8)*AQST + k0 + qc];
            uint32_t a2 = Qs[(m0+qr)*AQST + k0 + 4 + qc];
            uint32_t a3 = Qs[(m0+qr+8)*AQST + k0 + 4 + qc];
#pragma unroll
            for (int nt = 0; nt < 8; nt++) {
                int n = wn*64 + nt*8 + qr;
                uint32_t b0 = Kb[n*AKST + k0 + qc];
                uint32_t b1 = Kb[n*AKST + k0 + 4 + qc];
                mma_tf32(c[nt][0], c[nt][1], c[nt][2], c[nt][3], a0, a1, a2, a3, b0, b1);
            }
        }
        // normalized e + AM reds
#pragma unroll
        for (int nt = 0; nt < 8; nt++) {
            int col = kt*128 + wn*64 + nt*8 + 2*qc;
            float2 cl0 = *(const float2*)(CLr0 + col);
            float2 cl1 = *(const float2*)(CLr1 + col);
            c[nt][0] = __expf(c[nt][0]*scale + cl0.x - mf0) * if0;
            c[nt][1] = __expf(c[nt][1]*scale + cl0.y - mf0) * if0;
            c[nt][2] = __expf(c[nt][2]*scale + cl1.x - mf1) * if1;
            c[nt][3] = __expf(c[nt][3]*scale + cl1.y - mf1) * if1;
            red_add_v2(AM + ((size_t)(b*NQ + q0 + m0 + qr))*NKV + col,
                       c[nt][0]*0.0625f, c[nt][1]*0.0625f);
            red_add_v2(AM + ((size_t)(b*NQ + q0 + m0 + qr + 8))*NKV + col,
                       c[nt][2]*0.0625f, c[nt][3]*0.0625f);
        }
        __syncthreads();                   // KA reads + prev Es reads done
        if (kt < 7) CPA(Kbase, kt + 1, kaBase);   // pending: V(kt), K(kt+1)
        if (wn == 0) {
#pragma unroll
            for (int nt = 0; nt < 8; nt++) {
                int cc = nt*8 + 2*qc;
                *(float2*)(Es + (m0+qr)*AEST + cc)   = make_float2(c[nt][0], c[nt][1]);
                *(float2*)(Es + (m0+qr+8)*AEST + cc) = make_float2(c[nt][2], c[nt][3]);
            }
        }
        if (kt < 7) { CP_WAIT(1); } else { CP_WAIT(0); }   // V(kt) ready
        __syncthreads();                   // Es-A + V visible

        const uint32_t* Esu = (const uint32_t*)Es;
        const uint32_t* Vb  = (const uint32_t*)KB;
#pragma unroll
        for (int sub = 0; sub < 2; sub++) {
            if (sub == 1) {
                __syncthreads();           // Es-A reads done
                if (wn == 1) {
#pragma unroll
                    for (int nt = 0; nt < 8; nt++) {
                        int cc = nt*8 + 2*qc;
                        *(float2*)(Es + (m0+qr)*AEST + cc)   = make_float2(c[nt][0], c[nt][1]);
                        *(float2*)(Es + (m0+qr+8)*AEST + cc) = make_float2(c[nt][2], c[nt][3]);
                    }
                }
                __syncthreads();           // Es-B ready
            }
#pragma unroll
            for (int ks = 0; ks < 8; ks++) {
                int kl = ks * 8;
                uint32_t a0 = Esu[(am0+qr)*AEST + kl + qc];
                uint32_t a1 = Esu[(am0+qr+8)*AEST + kl + qc];
                uint32_t a2 = Esu[(am0+qr)*AEST + kl + 4 + qc];
                uint32_t a3 = Esu[(am0+qr+8)*AEST + kl + 4 + qc];
#pragma unroll
                for (int tt = 0; tt < 4; tt++) {
                    int dcol = wd*32 + tt*8 + qr;
                    uint32_t b0 = Vb[(sub*64 + kl + qc)*AKST + dcol];
                    uint32_t b1 = Vb[(sub*64 + kl + 4 + qc)*AKST + dcol];
                    mma_tf32(o[tt][0], o[tt][1], o[tt][2], o[tt][3], a0, a1, a2, a3, b0, b1);
                }
            }
        }
        __syncthreads();                   // KB reads done
        if (kt < 7) {
            CPA(Vbase, kt + 1, kbBase);    // pending: K(kt+1), V(kt+1)
            CP_WAIT(1);                    // K(kt+1) ready
            __syncthreads();
        }
    }

    // write AO (already normalized)
#pragma unroll
    for (int tt = 0; tt < 4; tt++) {
        int col = h*HD + wd*32 + tt*8 + 2*qc;
        *(float2*)(AO + ((size_t)(b*NQ + q0 + am0 + qr))*DIM + col) =
            make_float2(o[tt][0], o[tt][1]);
        *(float2*)(AO + ((size_t)(b*NQ + q0 + am0 + qr + 8))*DIM + col) =
            make_float2(o[tt][2], o[tt][3]);
    }
}

// ---------------------------------------------------------------------------
extern "C" void kernel_launch(void* const* d_in, const int* in_sizes, int n_in,
                              void* d_out, int out_size) {
    const float* query = (const float*)d_in[0];
    const float* kv    = (const float*)d_in[1];
    const float* cl    = (const float*)d_in[2];
    const float* Wq    = (const float*)d_in[3];
    const float* bq    = (const float*)d_in[4];
    const float* Wk    = (const float*)d_in[5];
    const float* bk    = (const float*)d_in[6];
    const float* Wv    = (const float*)d_in[7];
    const float* bv    = (const float*)d_in[8];
    const float* Wo    = (const float*)d_in[9];
    const float* bo    = (const float*)d_in[10];

    float* out_uq = (float*)d_out;
    float* out_am = out_uq + (size_t)BB*NQ*NKV;

    float *gQ, *gK, *gV, *gAO;
    cudaGetSymbolAddress((void**)&gQ,  g_Q);
    cudaGetSymbolAddress((void**)&gK,  g_K);
    cudaGetSymbolAddress((void**)&gV,  g_V);
    cudaGetSymbolAddress((void**)&gAO, g_AO);

    const int smem_attn = ASM_WORDS * (int)sizeof(float);   // ~104 KB
    cudaFuncSetAttribute(attn_kernel, cudaFuncAttributeMaxDynamicSharedMemorySize, smem_attn);
    cudaFuncSetAttribute(gemm_mma, cudaFuncAttributeMaxDynamicSharedMemorySize, SMEM_G);
    cudaFuncSetAttribute(qkv_zero_kernel, cudaFuncAttributeMaxDynamicSharedMemorySize, SMEM_G);

    qkv_zero_kernel<<<1792, 256, SMEM_G>>>(query, kv, Wq, bq, Wk, bk, Wv, bv,
                                           gQ, gK, gV,
                                           (float4*)out_am, BB*NQ*NKV/4);

    attn_kernel<<<BB*NH*(NQ/AQT), 256, smem_attn>>>(gQ, gK, gV, cl, gAO, out_am);

    dim3 gg(DIM/128, M_TOT/128);   // (8, 64)
    gemm_mma<<<gg, 256, SMEM_G>>>(gAO, Wo, bo, out_uq);
}

// round 9
// speedup vs baseline: 7.4783x; 1.0707x over previous
#include <cuda_runtime.h>
#include <cstdint>

#define BB 8
#define NQ 1024
#define NKV 1024
#define DIM 1024
#define NH 16
#define HD 64
#define M_TOT (BB*NQ)   // 8192

// attention tiling
#define AQT 64          // q rows per block
#define AQST 68         // Q smem stride (tf32 words)
#define AKST 68         // K/V smem stride (f32 words)
#define AEST 68         // e-stage stride
#define AKW (128*AKST)  // one K/V buffer (words)

// Scratch (allocation-free rule: __device__ globals)
__device__ float g_Q [M_TOT*DIM];
__device__ float g_K [M_TOT*DIM];
__device__ float g_V [M_TOT*DIM];
__device__ float g_AO[M_TOT*DIM];

// ---------------------------------------------------------------------------
__device__ __forceinline__ uint32_t smem_u32(const void* p) {
    uint32_t a;
    asm("{ .reg .u64 t; cvta.to.shared.u64 t, %1; cvt.u32.u64 %0, t; }" : "=r"(a) : "l"(p));
    return a;
}
__device__ __forceinline__ uint32_t f2tf32(float x) {
    uint32_t u;
    asm("cvt.rna.tf32.f32 %0, %1;" : "=r"(u) : "f"(x));
    return u;
}
__device__ __forceinline__ void mma_tf32(float& c0, float& c1, float& c2, float& c3,
                                         uint32_t a0, uint32_t a1, uint32_t a2, uint32_t a3,
                                         uint32_t b0, uint32_t b1) {
    asm volatile(
        "mma.sync.aligned.m16n8k8.row.col.f32.tf32.tf32.f32 "
        "{%0,%1,%2,%3}, {%4,%5,%6,%7}, {%8,%9}, {%0,%1,%2,%3};"
        : "+f"(c0), "+f"(c1), "+f"(c2), "+f"(c3)
        : "r"(a0), "r"(a1), "r"(a2), "r"(a3), "r"(b0), "r"(b1));
}
// tf32 fragment gather: one LDSM.x4 = four 8x4-tf32 tiles (16B rows)
__device__ __forceinline__ void ldsm4(uint32_t& r0, uint32_t& r1, uint32_t& r2, uint32_t& r3,
                                      uint32_t addr) {
    asm volatile("ldmatrix.sync.aligned.m8n8.x4.shared.b16 {%0,%1,%2,%3}, [%4];"
                 : "=r"(r0), "=r"(r1), "=r"(r2), "=r"(r3) : "r"(addr));
}
__device__ __forceinline__ void red_add_v2(float* p, float x, float y) {
    asm volatile("red.global.add.v2.f32 [%0], {%1,%2};"
                 :: "l"(p), "f"(x), "f"(y) : "memory");
}
__device__ __forceinline__ void cpasync16(uint32_t dst, const void* src) {
    asm volatile("cp.async.ca.shared.global [%0], [%1], 16;" :: "r"(dst), "l"(src) : "memory");
}
#define CP_COMMIT() asm volatile("cp.async.commit_group;" ::: "memory")
#define CP_WAIT(n)  asm volatile("cp.async.wait_group %0;" :: "n"(n) : "memory")

// ---------------------------------------------------------------------------
// GEMM body: Y[128x128 tile] = X @ W^T + bias. 256 thr, ldmatrix fragments.
// ---------------------------------------------------------------------------
#define GST 36
#define GBUF (128*GST)
#define SMEM_G (512 + 4*GBUF*4)

__device__ __forceinline__
void gemm_body(const float* __restrict__ X, const float* __restrict__ W,
               const float* __restrict__ bias, float* __restrict__ Y,
               int bx, int by) {
    extern __shared__ float sm[];
    float* bias_s = sm;
    uint32_t* As = (uint32_t*)(sm + 128);
    uint32_t* Bs = As + 2*GBUF;

    int t = threadIdx.x, lane = t & 31, wid = t >> 5;
    int bm = by * 128, bn = bx * 128;
    int wm = wid & 3, wn = wid >> 2;

    if (t < 128) bias_s[t] = bias[bn + t];

    int r0g = t >> 3;
    int c4 = t & 7;

    float4 ra[4], rb[4];
    auto LDG = [&](int kt) {
#pragma unroll
        for (int i = 0; i < 4; i++) {
            int r = r0g + 32*i;
            ra[i] = *(const float4*)(X + (size_t)(bm + r)*DIM + kt*32 + c4*4);
            rb[i] = *(const float4*)(W + (size_t)(bn + r)*DIM + kt*32 + c4*4);
        }
    };
    auto STS = [&](int p) {
#pragma unroll
        for (int i = 0; i < 4; i++) {
            int r = r0g + 32*i;
            uint32_t* pa = As + p*GBUF + r*GST + c4*4;
            uint32_t* pb = Bs + p*GBUF + r*GST + c4*4;
            pa[0] = f2tf32(ra[i].x); pa[1] = f2tf32(ra[i].y);
            pa[2] = f2tf32(ra[i].z); pa[3] = f2tf32(ra[i].w);
            pb[0] = f2tf32(rb[i].x); pb[1] = f2tf32(rb[i].y);
            pb[2] = f2tf32(rb[i].z); pb[3] = f2tf32(rb[i].w);
        }
    };

    float c[2][8][4];
#pragma unroll
    for (int i = 0; i < 2; i++)
#pragma unroll
        for (int j = 0; j < 8; j++)
#pragma unroll
            for (int k = 0; k < 4; k++) c[i][j][k] = 0.f;

    LDG(0); STS(0);
    __syncthreads();

    // ldmatrix per-thread base offsets (bytes)
    uint32_t AsU = smem_u32(As), BsU = smem_u32(Bs);
    int aRow = wm*32 + ((lane>>3)&1)*8 + (lane&7);   // + tm*16
    uint32_t aoff = (uint32_t)(aRow*GST + (lane>>4)*4) * 4u;
    int bRow = wn*64 + (lane>>4)*8 + (lane&7);       // + p2*16
    uint32_t boff = (uint32_t)(bRow*GST + ((lane>>3)&1)*4) * 4u;

    for (int kt = 0; kt < DIM/32; kt++) {
        int p = kt & 1;
        if (kt < DIM/32 - 1) LDG(kt + 1);
        uint32_t pb = (uint32_t)(p*GBUF)*4u;
#pragma unroll
        for (int s = 0; s < 4; s++) {
            uint32_t af[2][4], bf[8][2];
#pragma unroll
            for (int tm = 0; tm < 2; tm++)
                ldsm4(af[tm][0], af[tm][1], af[tm][2], af[tm][3],
                      AsU + pb + aoff + (uint32_t)(tm*16*GST)*4u + s*32u);
#pragma unroll
            for (int p2 = 0; p2 < 4; p2++)
                ldsm4(bf[2*p2][0], bf[2*p2][1], bf[2*p2+1][0], bf[2*p2+1][1],
                      BsU + pb + boff + (uint32_t)(p2*16*GST)*4u + s*32u);
#pragma unroll
            for (int tm = 0; tm < 2; tm++)
#pragma unroll
                for (int tn = 0; tn < 8; tn++)
                    mma_tf32(c[tm][tn][0], c[tm][tn][1], c[tm][tn][2], c[tm][tn][3],
                             af[tm][0], af[tm][1], af[tm][2], af[tm][3],
                             bf[tn][0], bf[tn][1]);
        }
        if (kt < DIM/32 - 1) STS(p ^ 1);
        __syncthreads();
    }

    int qr = lane >> 2, qc = lane & 3;
#pragma unroll
    for (int tm = 0; tm < 2; tm++) {
        int row = bm + wm*32 + tm*16 + qr;
#pragma unroll
        for (int tn = 0; tn < 8; tn++) {
            int col = wn*64 + tn*8 + qc*2;
            float2 v0 = { c[tm][tn][0] + bias_s[col], c[tm][tn][1] + bias_s[col+1] };
            float2 v1 = { c[tm][tn][2] + bias_s[col], c[tm][tn][3] + bias_s[col+1] };
            *(float2*)(Y + (size_t)row*DIM + bn + col)     = v0;
            *(float2*)(Y + (size_t)(row+8)*DIM + bn + col) = v1;
        }
    }
}

// Fused QKV projections + AM zeroing
__global__ __launch_bounds__(256, 2)
void qkv_zero_kernel(const float* __restrict__ query, const float* __restrict__ kv,
                     const float* __restrict__ Wq, const float* __restrict__ bq,
                     const float* __restrict__ Wk, const float* __restrict__ bk,
                     const float* __restrict__ Wv, const float* __restrict__ bv,
                     float* __restrict__ gQ, float* __restrict__ gK, float* __restrict__ gV,
                     float4* __restrict__ am4, int n4) {
    int g = blockIdx.x;
    if (g >= 1536) {
        float4 z = {0.f, 0.f, 0.f, 0.f};
        for (int i = (g - 1536)*256 + threadIdx.x; i < n4; i += 256*256) am4[i] = z;
        return;
    }
    int which = g >> 9;
    int bx = g & 7, by = (g & 511) >> 3;
    const float* X    = (which == 0) ? query : kv;
    const float* W    = (which == 0) ? Wq : (which == 1 ? Wk : Wv);
    const float* bias = (which == 0) ? bq : (which == 1 ? bk : bv);
    float*       Y    = (which == 0) ? gQ : (which == 1 ? gK : gV);
    gemm_body(X, W, bias, Y, bx, by);
}

__global__ __launch_bounds__(256, 2)
void gemm_mma(const float* __restrict__ X, const float* __restrict__ W,
              const float* __restrict__ bias, float* __restrict__ Y) {
    gemm_body(X, W, bias, Y, blockIdx.x, blockIdx.y);
}

// ---------------------------------------------------------------------------
// Flash-style attention (R8 structure) with ldmatrix fragment loads.
// ---------------------------------------------------------------------------
#define ASM_WORDS (AQT*AQST + 2*AKW + AQT*AEST + 384)

__global__ __launch_bounds__(256, 2)
void attn_kernel(const float* __restrict__ Q, const float* __restrict__ K,
                 const float* __restrict__ V, const float* __restrict__ CL,
                 float* __restrict__ AO, float* __restrict__ AM) {
    extern __shared__ float sm[];
    float* Qsf = sm;                 // 64*AQST (tf32 bits)
    float* KA  = Qsf + AQT*AQST;     // 128*AKST
    float* KB  = KA + AKW;           // 128*AKST
    float* Es  = KB + AKW;           // 64*AEST
    float* Mw  = Es + AQT*AEST;      // [2][64]
    float* Sw  = Mw + 128;           // [2][64]
    float* Mf  = Sw + 128;           // [64]
    float* If_ = Mf + 64;            // [64]

    uint32_t qsU = smem_u32(Qsf);
    uint32_t kaBase = smem_u32(KA), kbBase = smem_u32(KB);
    uint32_t esU = smem_u32(Es);

    int blk = blockIdx.x;
    int qt = blk & 15;
    int h  = (blk >> 4) & 15;
    int b  = blk >> 8;
    int q0 = qt * AQT;
    int t  = threadIdx.x;
    int lane = t & 31, wid = t >> 5;
    int qr = lane >> 2, qc = lane & 3;
    int wm = wid & 3, wn = wid >> 2;   // QK: m-tile (16), k-col half (64)
    int m0 = wm * 16;
    const float scale = 0.125f;

    int ldr = t >> 4;                  // 0..15
    int ldd = t & 15;                  // 0..15

    const float* Kbase = K + ((size_t)(b*NKV))*DIM + h*HD;
    const float* Vbase = V + ((size_t)(b*NKV))*DIM + h*HD;

    auto CPA = [&](const float* gsrc, int kt, uint32_t sbase) {
#pragma unroll
        for (int i = 0; i < 8; i++) {
            int r = ldr + i*16;
            cpasync16(sbase + (uint32_t)(r*AKST + ldd*4)*4u,
                      gsrc + (size_t)(kt*128 + r)*DIM + ldd*4);
        }
        CP_COMMIT();
    };

    // ldmatrix per-thread offsets (bytes)
    // QK a-frag (m16 at m0, stride AQST)
    uint32_t aoffQ = (uint32_t)((m0 + ((lane>>3)&1)*8 + (lane&7))*AQST + (lane>>4)*4) * 4u;
    // QK b-frag (rows wn*64 + p2*16, stride AKST)
    uint32_t boffK = (uint32_t)((wn*64 + (lane>>4)*8 + (lane&7))*AKST + ((lane>>3)&1)*4) * 4u;

    // Q tile -> tf32 smem
#pragma unroll
    for (int i = 0; i < 4; i++) {
        int f = t + i*256;
        int qi = f >> 4, d4 = f & 15;
        float4 v = *(const float4*)(Q + ((size_t)(b*NQ + q0 + qi))*DIM + h*HD + d4*4);
        uint32_t* p = (uint32_t*)Qsf + qi*AQST + d4*4;
        p[0] = f2tf32(v.x); p[1] = f2tf32(v.y); p[2] = f2tf32(v.z); p[3] = f2tf32(v.w);
    }
    CPA(Kbase, 0, kaBase);

    const float* CLr0 = CL + ((size_t)(b*NQ + q0 + m0 + qr))*NKV;
    const float* CLr1 = CLr0 + (size_t)8*NKV;

    float m_a = -1e30f, m_b = -1e30f, s_a = 0.f, s_b = 0.f;

    // QK^T compute for one 128-chunk from buffer at kBufU
    auto QK_CHUNK = [&](uint32_t kBufU, float c[8][4]) {
#pragma unroll
        for (int i = 0; i < 8; i++)
#pragma unroll
            for (int j = 0; j < 4; j++) c[i][j] = 0.f;
#pragma unroll
        for (int ks = 0; ks < 8; ks++) {
            uint32_t af0, af1, af2, af3;
            ldsm4(af0, af1, af2, af3, qsU + aoffQ + ks*32u);
            uint32_t bf[8][2];
#pragma unroll
            for (int p2 = 0; p2 < 4; p2++)
                ldsm4(bf[2*p2][0], bf[2*p2][1], bf[2*p2+1][0], bf[2*p2+1][1],
                      kBufU + boffK + (uint32_t)(p2*16*AKST)*4u + ks*32u);
#pragma unroll
            for (int nt = 0; nt < 8; nt++)
                mma_tf32(c[nt][0], c[nt][1], c[nt][2], c[nt][3],
                         af0, af1, af2, af3, bf[nt][0], bf[nt][1]);
        }
    };

    // ================= pass 1: scores + online (m, s) =================
    for (int kt = 0; kt < 8; kt++) {
        uint32_t kBufU = (kt & 1) ? kbBase : kaBase;
        if (kt < 7) { CPA(Kbase, kt + 1, (kt & 1) ? kaBase : kbBase); CP_WAIT(1); }
        else        { CP_WAIT(0); }
        __syncthreads();

        float c[8][4];
        QK_CHUNK(kBufU, c);

        float cma = -1e30f, cmb = -1e30f;
#pragma unroll
        for (int nt = 0; nt < 8; nt++) {
            int col = kt*128 + wn*64 + nt*8 + 2*qc;
            float2 cl0 = *(const float2*)(CLr0 + col);
            float2 cl1 = *(const float2*)(CLr1 + col);
            c[nt][0] = c[nt][0]*scale + cl0.x;
            c[nt][1] = c[nt][1]*scale + cl0.y;
            c[nt][2] = c[nt][2]*scale + cl1.x;
            c[nt][3] = c[nt][3]*scale + cl1.y;
            cma = fmaxf(cma, fmaxf(c[nt][0], c[nt][1]));
            cmb = fmaxf(cmb, fmaxf(c[nt][2], c[nt][3]));
        }
#pragma unroll
        for (int o = 1; o <= 2; o <<= 1) {
            cma = fmaxf(cma, __shfl_xor_sync(0xffffffffu, cma, o));
            cmb = fmaxf(cmb, __shfl_xor_sync(0xffffffffu, cmb, o));
        }
        float mna = fmaxf(m_a, cma), mnb = fmaxf(m_b, cmb);
        float sea = 0.f, seb = 0.f;
#pragma unroll
        for (int nt = 0; nt < 8; nt++) {
            sea += __expf(c[nt][0] - mna) + __expf(c[nt][1] - mna);
            seb += __expf(c[nt][2] - mnb) + __expf(c[nt][3] - mnb);
        }
#pragma unroll
        for (int o = 1; o <= 2; o <<= 1) {
            sea += __shfl_xor_sync(0xffffffffu, sea, o);
            seb += __shfl_xor_sync(0xffffffffu, seb, o);
        }
        s_a = s_a * __expf(m_a - mna) + sea;  m_a = mna;
        s_b = s_b * __expf(m_b - mnb) + seb;  m_b = mnb;
    }

    if (qc == 0) {
        Mw[wn*64 + m0 + qr]     = m_a;  Mw[wn*64 + m0 + qr + 8] = m_b;
        Sw[wn*64 + m0 + qr]     = s_a;  Sw[wn*64 + m0 + qr + 8] = s_b;
    }
    __syncthreads();
    if (t < 64) {
        float mv0 = Mw[t], mv1 = Mw[64 + t];
        float m = fmaxf(mv0, mv1);
        float s = Sw[t]*__expf(mv0 - m) + Sw[64 + t]*__expf(mv1 - m);
        Mf[t] = m;  If_[t] = 1.0f / s;
    }
    CPA(Kbase, 0, kaBase);
    CPA(Vbase, 0, kbBase);
    CP_WAIT(1);
    __syncthreads();

    float mf0 = Mf[m0 + qr], mf1 = Mf[m0 + qr + 8];
    float if0 = If_[m0 + qr], if1 = If_[m0 + qr + 8];

    // AV mapping: wm2 m-tile (4x16), wd d-half (2x32)
    int wm2 = wid & 3, wd = wid >> 2;
    int am0 = wm2 * 16;
    // Es a-frag offset (rows am0, stride AEST)
    uint32_t aoffE = (uint32_t)((am0 + ((lane>>3)&1)*8 + (lane&7))*AEST + (lane>>4)*4) * 4u;

    float o[4][4];
#pragma unroll
    for (int i = 0; i < 4; i++)
#pragma unroll
        for (int j = 0; j < 4; j++) o[i][j] = 0.f;

    // ================= pass 2: recompute + AM red + AV =================
    for (int kt = 0; kt < 8; kt++) {
        float c[8][4];
        QK_CHUNK(kaBase, c);

#pragma unroll
        for (int nt = 0; nt < 8; nt++) {
            int col = kt*128 + wn*64 + nt*8 + 2*qc;
            float2 cl0 = *(const float2*)(CLr0 + col);
            float2 cl1 = *(const float2*)(CLr1 + col);
            c[nt][0] = __expf(c[nt][0]*scale + cl0.x - mf0) * if0;
            c[nt][1] = __expf(c[nt][1]*scale + cl0.y - mf0) * if0;
            c[nt][2] = __expf(c[nt][2]*scale + cl1.x - mf1) * if1;
            c[nt][3] = __expf(c[nt][3]*scale + cl1.y - mf1) * if1;
            red_add_v2(AM + ((size_t)(b*NQ + q0 + m0 + qr))*NKV + col,
                       c[nt][0]*0.0625f, c[nt][1]*0.0625f);
            red_add_v2(AM + ((size_t)(b*NQ + q0 + m0 + qr + 8))*NKV + col,
                       c[nt][2]*0.0625f, c[nt][3]*0.0625f);
        }
        __syncthreads();                   // KA reads + prev Es reads done
        if (kt < 7) CPA(Kbase, kt + 1, kaBase);
        if (wn == 0) {
#pragma unroll
            for (int nt = 0; nt < 8; nt++) {
                int cc = nt*8 + 2*qc;
                *(float2*)(Es + (m0+qr)*AEST + cc)   = make_float2(c[nt][0], c[nt][1]);
                *(float2*)(Es + (m0+qr+8)*AEST + cc) = make_float2(c[nt][2], c[nt][3]);
            }
        }
        if (kt < 7) { CP_WAIT(1); } else { CP_WAIT(0); }
        __syncthreads();                   // Es-A + V visible

        const uint32_t* Vb  = (const uint32_t*)KB;
#pragma unroll
        for (int sub = 0; sub < 2; sub++) {
            if (sub == 1) {
                __syncthreads();
                if (wn == 1) {
#pragma unroll
                    for (int nt = 0; nt < 8; nt++) {
                        int cc = nt*8 + 2*qc;
                        *(float2*)(Es + (m0+qr)*AEST + cc)   = make_float2(c[nt][0], c[nt][1]);
                        *(float2*)(Es + (m0+qr+8)*AEST + cc) = make_float2(c[nt][2], c[nt][3]);
                    }
                }
                __syncthreads();
            }
#pragma unroll
            for (int ks = 0; ks < 8; ks++) {
                int kl = ks * 8;
                uint32_t a0, a1, a2, a3;
                ldsm4(a0, a1, a2, a3, esU + aoffE + ks*32u);
#pragma unroll
                for (int tt = 0; tt < 4; tt++) {
                    int dcol = wd*32 + tt*8 + qr;
                    uint32_t b0 = Vb[(sub*64 + kl + qc)*AKST + dcol];
                    uint32_t b1 = Vb[(sub*64 + kl + 4 + qc)*AKST + dcol];
                    mma_tf32(o[tt][0], o[tt][1], o[tt][2], o[tt][3], a0, a1, a2, a3, b0, b1);
                }
            }
        }
        __syncthreads();                   // KB reads done
        if (kt < 7) {
            CPA(Vbase, kt + 1, kbBase);
            CP_WAIT(1);
            __syncthreads();
        }
    }

    // write AO (already normalized)
#pragma unroll
    for (int tt = 0; tt < 4; tt++) {
        int col = h*HD + wd*32 + tt*8 + 2*qc;
        *(float2*)(AO + ((size_t)(b*NQ + q0 + am0 + qr))*DIM + col) =
            make_float2(o[tt][0], o[tt][1]);
        *(float2*)(AO + ((size_t)(b*NQ + q0 + am0 + qr + 8))*DIM + col) =
            make_float2(o[tt][2], o[tt][3]);
    }
}

// ---------------------------------------------------------------------------
extern "C" void kernel_launch(void* const* d_in, const int* in_sizes, int n_in,
                              void* d_out, int out_size) {
    const float* query = (const float*)d_in[0];
    const float* kv    = (const float*)d_in[1];
    const float* cl    = (const float*)d_in[2];
    const float* Wq    = (const float*)d_in[3];
    const float* bq    = (const float*)d_in[4];
    const float* Wk    = (const float*)d_in[5];
    const float* bk    = (const float*)d_in[6];
    const float* Wv    = (const float*)d_in[7];
    const float* bv    = (const float*)d_in[8];
    const float* Wo    = (const float*)d_in[9];
    const float* bo    = (const float*)d_in[10];

    float* out_uq = (float*)d_out;
    float* out_am = out_uq + (size_t)BB*NQ*NKV;

    float *gQ, *gK, *gV, *gAO;
    cudaGetSymbolAddress((void**)&gQ,  g_Q);
    cudaGetSymbolAddress((void**)&gK,  g_K);
    cudaGetSymbolAddress((void**)&gV,  g_V);
    cudaGetSymbolAddress((void**)&gAO, g_AO);

    const int smem_attn = ASM_WORDS * (int)sizeof(float);   // ~104 KB
    cudaFuncSetAttribute(attn_kernel, cudaFuncAttributeMaxDynamicSharedMemorySize, smem_attn);
    cudaFuncSetAttribute(gemm_mma, cudaFuncAttributeMaxDynamicSharedMemorySize, SMEM_G);
    cudaFuncSetAttribute(qkv_zero_kernel, cudaFuncAttributeMaxDynamicSharedMemorySize, SMEM_G);

    qkv_zero_kernel<<<1792, 256, SMEM_G>>>(query, kv, Wq, bq, Wk, bk, Wv, bv,
                                           gQ, gK, gV,
                                           (float4*)out_am, BB*NQ*NKV/4);

    attn_kernel<<<BB*NH*(NQ/AQT), 256, smem_attn>>>(gQ, gK, gV, cl, gAO, out_am);

    dim3 gg(DIM/128, M_TOT/128);   // (8, 64)
    gemm_mma<<<gg, 256, SMEM_G>>>(gAO, Wo, bo, out_uq);
}